// round 13
// baseline (speedup 1.0000x reference)
#include <cuda_runtime.h>
#include <cuda_bf16.h>
#include <math.h>
#include <stdint.h>

// ============================================================================
// fp32 scratch  (Ob/Oc have 4 k-split partial buffers)
// ============================================================================
static constexpr size_t OSZ_B = (size_t)2*3136*64;    // one split buffer
static constexpr size_t OSZ_C = (size_t)2*12544*32;

static constexpr size_t SZ_X1A = (size_t)2*784*64;
static constexpr size_t SZ_OA  = (size_t)2*784*64;
static constexpr size_t SZ_X1B = (size_t)2*3136*64;
static constexpr size_t SZ_OB  = 4*OSZ_B;             // [split][b][N][H]
static constexpr size_t SZ_X1C = (size_t)2*12544*32;
static constexpr size_t SZ_OC  = 4*OSZ_C;             // [split][b][N][H]
static constexpr size_t SZ_Y1  = (size_t)2*3136*32;
static constexpr size_t SZ_Y2  = (size_t)2*12544*16;
static constexpr size_t SZ_Y3  = (size_t)2*50176*8;
static constexpr size_t SZ_BS  = (size_t)2*512;       // per-stage block partials

static constexpr size_t OFF_X1A = 0;
static constexpr size_t OFF_OA  = OFF_X1A + SZ_X1A;
static constexpr size_t OFF_X1B = OFF_OA  + SZ_OA;
static constexpr size_t OFF_OB  = OFF_X1B + SZ_X1B;
static constexpr size_t OFF_X1C = OFF_OB  + SZ_OB;
static constexpr size_t OFF_OC  = OFF_X1C + SZ_X1C;
static constexpr size_t OFF_Y1  = OFF_OC  + SZ_OC;
static constexpr size_t OFF_Y2  = OFF_Y1  + SZ_Y1;
static constexpr size_t OFF_Y3  = OFF_Y2  + SZ_Y2;
static constexpr size_t OFF_BSA = OFF_Y3  + SZ_Y3;
static constexpr size_t OFF_BSB = OFF_BSA + SZ_BS;
static constexpr size_t OFF_BSC = OFF_BSB + SZ_BS;
static constexpr size_t SCRATCH_TOTAL = OFF_BSC + SZ_BS;
__device__ __align__(16) float g_scratch[SCRATCH_TOTAL];

// ============================================================================
// bf16 scratch: x2 row-major + x2 transposed per stage (padded rows zeroed)
// ============================================================================
static constexpr size_t BOFF_X2A = 0;                                   // 2*256*64
static constexpr size_t BOFF_TA  = BOFF_X2A + (size_t)2*256*64;         // 2*64*256
static constexpr size_t BOFF_X2B = BOFF_TA  + (size_t)2*64*256;         // 2*832*64
static constexpr size_t BOFF_TB  = BOFF_X2B + (size_t)2*832*64;         // 2*64*832
static constexpr size_t BOFF_X2C = BOFF_TB  + (size_t)2*64*832;         // 2*3136*32
static constexpr size_t BOFF_TC  = BOFF_X2C + (size_t)2*3136*32;        // 2*32*3136
static constexpr size_t BSCRATCH_TOTAL = BOFF_TC + (size_t)2*32*3136;
__device__ __align__(16) __nv_bfloat16 g_bf[BSCRATCH_TOTAL];

#define MMA_BF16(d, a, b)                                                      \
    asm volatile(                                                              \
        "mma.sync.aligned.m16n8k16.row.col.f32.bf16.bf16.f32 "                 \
        "{%0,%1,%2,%3},{%4,%5,%6,%7},{%8,%9},{%0,%1,%2,%3};"                   \
        : "+f"((d)[0]), "+f"((d)[1]), "+f"((d)[2]), "+f"((d)[3])               \
        : "r"((a)[0]), "r"((a)[1]), "r"((a)[2]), "r"((a)[3]),                  \
          "r"((b)[0]), "r"((b)[1]))

__device__ __forceinline__ void cp16(uint32_t saddr, const void* gptr) {
    asm volatile("cp.async.ca.shared.global [%0], [%1], 16;" :: "r"(saddr), "l"(gptr));
}
__device__ __forceinline__ uint32_t pack_bf2(float lo, float hi) {
    __nv_bfloat162 v = __floats2bfloat162_rn(lo, hi);
    return *reinterpret_cast<uint32_t*>(&v);
}

// Warp-0 deterministic partial-sum (identical everywhere -> identical Z).
__device__ __forceinline__ float warp_sum_partials(const float* bs, int NB, int lane) {
    float z = 0.f;
    for (int i = lane; i < NB; i += 32) z += bs[i];
#pragma unroll
    for (int off = 16; off > 0; off >>= 1)
        z += __shfl_xor_sync(0xffffffffu, z, off);
    return z;
}

// ============================================================================
// Generic projection (NCHW source, coalesced): used only for CSA1's x2 (f0).
// ============================================================================
template<int C, int H>
__global__ void __launch_bounds__(256) proj_plain_kernel(
    const float* __restrict__ X, const float* __restrict__ W,
    __nv_bfloat16* __restrict__ outbf, __nv_bfloat16* __restrict__ outT,
    int N, int Np, size_t bstride)
{
    __shared__ float sw[C*H];
    const int tid = threadIdx.x;
    for (int i = tid; i < C*H; i += 256) sw[i] = W[i];
    __syncthreads();
    const int b = blockIdx.y;
    const int n = blockIdx.x * 32 + (tid & 31);
    const int ty = tid >> 5;
    constexpr int HP = H / 8;
    if (n >= Np) return;

    float acc[HP];
#pragma unroll
    for (int k = 0; k < HP; k++) acc[k] = 0.f;
    if (n < N) {
        const float* xb = X + (size_t)b * bstride;
        for (int c = 0; c < C; c++) {
            float v = xb[(size_t)c * N + n];
            const float* wr = &sw[c*H + ty*HP];
#pragma unroll
            for (int k = 0; k < HP; k++) acc[k] += v * wr[k];
        }
    }
    __nv_bfloat16* obf = outbf + ((size_t)b * Np + n) * H + ty * HP;
#pragma unroll
    for (int k = 0; k < HP; k += 2)
        *reinterpret_cast<uint32_t*>(obf + k) = pack_bf2(acc[k], acc[k+1]);
    __nv_bfloat16* ot = outT + (size_t)b * H * Np;
#pragma unroll
    for (int k = 0; k < HP; k++) ot[(size_t)(ty * HP + k) * Np + n] = __float2bfloat16(acc[k]);
}

// ============================================================================
// Norm-folded projection: In(n,c) = (sum_s O_s)(n,c)/Z + xres(n,c), out = In.W
// 512 threads: 16 px x 16 hg x 2 C-halves. Z from per-block partials.
// ============================================================================
template<int C, int H, int NSPLIT>
__global__ void __launch_bounds__(512) proj_norm_kernel(
    const float* __restrict__ O, size_t osz,
    const float* __restrict__ xres,
    const float* __restrict__ BS, int NB,
    const float* __restrict__ W,
    __nv_bfloat16* __restrict__ outbf, __nv_bfloat16* __restrict__ outT,
    int N, int Np)
{
    constexpr int PXB = 16;
    constexpr int PPX = PXB + 1;
    constexpr int HP  = H / 16;            // 4 (H=64) or 2 (H=32)
    __shared__ float sraw[C * PPX];
    __shared__ float sw[C * H];
    __shared__ float sacc[PXB * 16 * HP];
    __shared__ float sZ;
    const int tid = threadIdx.x;
    const int b = blockIdx.y;
    const int px0 = blockIdx.x * PXB;
    for (int i = tid; i < C*H; i += 512) sw[i] = W[i];
    if (tid < 32) {
        float z = warp_sum_partials(BS + (size_t)b * NB, NB, tid);
        if (tid == 0) sZ = 1.f / z;
    }
    __syncthreads();

    const float f = sZ;
    constexpr int C4 = C / 4;
    for (int i = tid; i < PXB * C4; i += 512) {
        int c4 = i % C4, px = i / C4;
        int n = px0 + px;
        float4 o4 = make_float4(0.f,0.f,0.f,0.f), r4 = o4;
        if (n < N) {
            size_t idx = ((size_t)b * N + n) * C + c4 * 4;
            o4 = *reinterpret_cast<const float4*>(O + idx);
#pragma unroll
            for (int s = 1; s < NSPLIT; s++) {
                float4 t = *reinterpret_cast<const float4*>(O + s * osz + idx);
                o4.x += t.x; o4.y += t.y; o4.z += t.z; o4.w += t.w;
            }
            r4 = *reinterpret_cast<const float4*>(xres + idx);
        }
        sraw[(c4*4+0) * PPX + px] = o4.x * f + r4.x;
        sraw[(c4*4+1) * PPX + px] = o4.y * f + r4.y;
        sraw[(c4*4+2) * PPX + px] = o4.z * f + r4.z;
        sraw[(c4*4+3) * PPX + px] = o4.w * f + r4.w;
    }
    __syncthreads();

    const int ch = tid >> 8;               // 0..1 C-half
    const int px = tid & (PXB - 1);
    const int hg = (tid >> 4) & 15;        // 0..15
    float acc[HP];
#pragma unroll
    for (int k = 0; k < HP; k++) acc[k] = 0.f;
#pragma unroll 4
    for (int c = ch * (C/2); c < (ch + 1) * (C/2); c++) {
        float v = sraw[c * PPX + px];
        if (HP == 4) {
            float4 w4 = *reinterpret_cast<const float4*>(&sw[c*H + hg*4]);
            acc[0] += v * w4.x; acc[1] += v * w4.y;
            acc[2] += v * w4.z; acc[3] += v * w4.w;
        } else {
            float2 w2 = *reinterpret_cast<const float2*>(&sw[c*H + hg*2]);
            acc[0] += v * w2.x; acc[1] += v * w2.y;
        }
    }
    if (ch == 1) {
#pragma unroll
        for (int k = 0; k < HP; k++) sacc[(hg * PXB + px) * HP + k] = acc[k];
    }
    __syncthreads();
    if (ch != 0) return;
    const int n = px0 + px;
    if (n >= Np) return;
#pragma unroll
    for (int k = 0; k < HP; k++) acc[k] += sacc[(hg * PXB + px) * HP + k];

    __nv_bfloat16* obf = outbf + ((size_t)b * Np + n) * H + hg * HP;
#pragma unroll
    for (int k = 0; k < HP; k += 2)
        *reinterpret_cast<uint32_t*>(obf + k) = pack_bf2(acc[k], acc[k+1]);
    __nv_bfloat16* ot = outT + (size_t)b * H * Np;
#pragma unroll
    for (int k = 0; k < HP; k++) ot[(size_t)(hg * HP + k) * Np + n] = __float2bfloat16(acc[k]);
}

// ============================================================================
// FA2-style bf16 flash CSA, fused X1 projection, no max stabilization.
// N2 k-split ACROSS blocks: blockIdx.z = split; split-private O buffer.
// ============================================================================
template<int H, int RB, int C>
__global__ void __launch_bounds__(RB*2) flash_fused_kernel(
    const float* __restrict__ X1src,          // [b][C][N1] NCHW
    const float* __restrict__ W1,             // [C][H]
    const __nv_bfloat16* __restrict__ X2bf,   // [b][N2p][H]
    const __nv_bfloat16* __restrict__ X2T,    // [b][H][N2p]
    float* __restrict__ x1out,                // [b][N1][H] fp32 residual
    float* __restrict__ Oout, float* __restrict__ blocksum,
    int N1, int N2, int N2p)
{
    constexpr int THREADS = RB * 2;
    constexpr int MB = 64;
    constexpr int PH = H + 8;
    constexpr int PM = MB + 8;
    constexpr int KSQ = H / 16;
    constexpr int NTS = MB / 8;
    constexpr int KSA = MB / 16;
    constexpr int NTO = H / 8;
    constexpr int CPR = H * 2 / 16;

    extern __shared__ char smraw[];
    __nv_bfloat16* sX1 = (__nv_bfloat16*)smraw;                 // RB*PH halves
    char* region = smraw + (size_t)RB * PH * 2;
    float* praw = (float*)region;                               // [C][RB]
    float* swp  = praw + C * RB;                                // [C][H]
    __nv_bfloat16* sX2 = (__nv_bfloat16*)region;                // 2*MB*PH (after proj)
    __nv_bfloat16* sT  = sX2 + 2 * MB * PH;                     // 2*H*PM

    const int b = blockIdx.y;
    const int split = blockIdx.z;
    const int NS = gridDim.z;
    const int row0 = blockIdx.x * RB;
    const int tid = threadIdx.x, w = tid >> 5, lane = tid & 31;
    const int g = lane >> 2, t4 = lane & 3;
    const int wrow = w * 16;

    float* Op = Oout + (size_t)split * 2 * N1 * H;   // split-private O buffer

    // ---- stage raw X1 source tile (coalesced) + weights
    for (int i = tid; i < C * RB; i += THREADS) {
        int c = i / RB, r = i % RB;
        int gr = row0 + r;
        praw[c * RB + r] = (gr < N1) ? X1src[(size_t)b * C * N1 + (size_t)c * N1 + gr] : 0.f;
    }
    for (int i = tid; i < C * H; i += THREADS) swp[i] = W1[i];
    __syncthreads();

    // ---- fused projection: each thread: one row, H/2 outputs
    {
        const int r  = tid % RB;
        const int hg = tid / RB;        // 0 or 1
        constexpr int HP2 = H / 2;
        const int h0 = hg * HP2;
        float acc[HP2];
#pragma unroll
        for (int k = 0; k < HP2; k++) acc[k] = 0.f;
        for (int c = 0; c < C; c++) {
            float v = praw[c * RB + r];
            const float* wr = swp + c * H + h0;
#pragma unroll
            for (int k = 0; k < HP2; k++) acc[k] += v * wr[k];
        }
#pragma unroll
        for (int k = 0; k < HP2; k += 2)
            *reinterpret_cast<uint32_t*>(sX1 + r * PH + h0 + k) = pack_bf2(acc[k], acc[k+1]);
        int gr = row0 + r;
        if (split == 0 && gr < N1) {
            float* dst = x1out + ((size_t)b * N1 + gr) * H + h0;
#pragma unroll
            for (int k = 0; k < HP2; k += 4)
                *reinterpret_cast<float4*>(dst + k) = make_float4(acc[k], acc[k+1], acc[k+2], acc[k+3]);
        }
    }
    __syncthreads();   // praw/swp dead; region reused by cp.async below

    const __nv_bfloat16* x2 = X2bf + (size_t)b * N2p * H;
    const __nv_bfloat16* xt = X2T  + (size_t)b * H * N2p;
    const int T = (N2 + MB - 1) / MB;
    const int t0 = (T * split) / NS;
    const int t1 = (T * (split + 1)) / NS;

    auto prefetch = [&](int t) {
        int buf = t & 1;
        uint32_t d2 = (uint32_t)__cvta_generic_to_shared(sX2 + buf * MB * PH);
        const __nv_bfloat16* src = x2 + (size_t)t * MB * H;
        for (int c = tid; c < MB * CPR; c += THREADS) {
            int r = c / CPR, k = c % CPR;
            cp16(d2 + (r * PH + k * 8) * 2, src + (size_t)r * H + k * 8);
        }
        uint32_t dT = (uint32_t)__cvta_generic_to_shared(sT + buf * H * PM);
        for (int c = tid; c < H * 8; c += THREADS) {
            int r = c / 8, k = c % 8;
            cp16(dT + (r * PM + k * 8) * 2, xt + (size_t)r * N2p + (size_t)t * MB + k * 8);
        }
        asm volatile("cp.async.commit_group;");
    };

    prefetch(t0);

    float s0 = 0.f, s1 = 0.f;
    float o[NTO][4];
#pragma unroll
    for (int nt = 0; nt < NTO; nt++)
#pragma unroll
        for (int k = 0; k < 4; k++) o[nt][k] = 0.f;

    for (int t = t0; t < t1; t++) {
        asm volatile("cp.async.wait_group 0;");
        __syncthreads();
        if (t + 1 < t1) prefetch(t + 1);
        const __nv_bfloat16* bX2 = sX2 + (t & 1) * MB * PH;
        const __nv_bfloat16* bT  = sT  + (t & 1) * H * PM;

        float sacc[NTS][4];
#pragma unroll
        for (int nt = 0; nt < NTS; nt++)
#pragma unroll
            for (int k = 0; k < 4; k++) sacc[nt][k] = 0.f;
#pragma unroll
        for (int ks = 0; ks < KSQ; ks++) {
            const int cb = ks * 16 + 2 * t4;
            uint32_t a[4];
            a[0] = *reinterpret_cast<const uint32_t*>(sX1 + (wrow + g) * PH + cb);
            a[1] = *reinterpret_cast<const uint32_t*>(sX1 + (wrow + g + 8) * PH + cb);
            a[2] = *reinterpret_cast<const uint32_t*>(sX1 + (wrow + g) * PH + cb + 8);
            a[3] = *reinterpret_cast<const uint32_t*>(sX1 + (wrow + g + 8) * PH + cb + 8);
#pragma unroll
            for (int nt = 0; nt < NTS; nt++) {
                uint32_t bb[2];
                bb[0] = *reinterpret_cast<const uint32_t*>(bX2 + (nt * 8 + g) * PH + cb);
                bb[1] = *reinterpret_cast<const uint32_t*>(bX2 + (nt * 8 + g) * PH + cb + 8);
                MMA_BF16(sacc[nt], a, bb);
            }
        }

        const int limit = N2 - t * MB;
        const bool full = (limit >= MB);

        // ---- P = exp(S) directly (scores bounded, no max needed)
        uint32_t pA[KSA][4];
#pragma unroll
        for (int nt = 0; nt < NTS; nt++) {
            int c0 = nt * 8 + 2 * t4;
            float p0 = (full || c0     < limit) ? __expf(sacc[nt][0]) : 0.f;
            float p1 = (full || c0 + 1 < limit) ? __expf(sacc[nt][1]) : 0.f;
            float p2 = (full || c0     < limit) ? __expf(sacc[nt][2]) : 0.f;
            float p3 = (full || c0 + 1 < limit) ? __expf(sacc[nt][3]) : 0.f;
            s0 += p0 + p1; s1 += p2 + p3;
            pA[nt >> 1][(nt & 1) * 2 + 0] = pack_bf2(p0, p1);
            pA[nt >> 1][(nt & 1) * 2 + 1] = pack_bf2(p2, p3);
        }

        // ---- O += P . X2 (no rescale)
#pragma unroll
        for (int ks = 0; ks < KSA; ks++) {
#pragma unroll
            for (int nt = 0; nt < NTO; nt++) {
                const int rb2 = (nt * 8 + g) * PM + ks * 16 + 2 * t4;
                uint32_t bb[2];
                bb[0] = *reinterpret_cast<const uint32_t*>(bT + rb2);
                bb[1] = *reinterpret_cast<const uint32_t*>(bT + rb2 + 8);
                MMA_BF16(o[nt], pA[ks], bb);
            }
        }
    }

    // ---- final row-sum reduce over t4 quad
    s0 += __shfl_xor_sync(0xffffffffu, s0, 1);
    s0 += __shfl_xor_sync(0xffffffffu, s0, 2);
    s1 += __shfl_xor_sync(0xffffffffu, s1, 1);
    s1 += __shfl_xor_sync(0xffffffffu, s1, 2);

    const int gr0 = row0 + wrow + g;
    const int gr1 = gr0 + 8;
    {
        if (gr0 < N1) {
            float* dst = Op + ((size_t)b * N1 + gr0) * H;
#pragma unroll
            for (int nt = 0; nt < NTO; nt++)
                *reinterpret_cast<float2*>(dst + nt * 8 + 2 * t4) = make_float2(o[nt][0], o[nt][1]);
        }
        if (gr1 < N1) {
            float* dst = Op + ((size_t)b * N1 + gr1) * H;
#pragma unroll
            for (int nt = 0; nt < NTO; nt++)
                *reinterpret_cast<float2*>(dst + nt * 8 + 2 * t4) = make_float2(o[nt][2], o[nt][3]);
        }
    }

    // ---- per-block deterministic Z partial (padded rows masked to 0)
    __syncthreads();                       // all warps past mainloop; smem free
    float* sRS = (float*)smraw;            // RB floats
    if (t4 == 0) {
        sRS[wrow + g]     = (gr0 < N1) ? s0 : 0.f;
        sRS[wrow + g + 8] = (gr1 < N1) ? s1 : 0.f;
    }
    __syncthreads();
    if (tid == 0) {
        float z = 0.f;
        for (int r = 0; r < RB; r++) z += sRS[r];
        blocksum[((size_t)b * NS + split) * gridDim.x + blockIdx.x] = z;
    }
}

// ============================================================================
// MSR with optional folded softmax-normalization (Z from block partials).
// BNS: number of base O k-split partials to sum.
// ============================================================================
__device__ __forceinline__ float4 f4fma(float4 a, float s, float4 acc) {
    acc.x += a.x * s; acc.y += a.y * s; acc.z += a.z * s; acc.w += a.w * s;
    return acc;
}

template<int CIN, int CHID, int COUT, bool HASBASE, bool PREVNORM, bool BASENORM, int BNS>
__global__ void __launch_bounds__(128) msr_kernel(
    const float* __restrict__ baseO, size_t bosz,
    const float* __restrict__ basex1,
    const float* __restrict__ baseBS, int baseNB,
    const float* __restrict__ prevO, const float* __restrict__ prevx1,
    const float* __restrict__ prevBS, int prevNB,
    const float* __restrict__ w1, const float* __restrict__ b1,
    const float* __restrict__ w2, const float* __restrict__ b2,
    float* __restrict__ out, int Hout, int Hin)
{
    __shared__ float sw1[CIN * CHID];
    __shared__ float sw2[CHID * COUT];
    __shared__ float sb1[CHID];
    __shared__ float sb2[COUT];
    __shared__ float sZp, sZb;
    const int tid = threadIdx.x;
    const int b = blockIdx.y;
    for (int i = tid; i < CIN * CHID; i += 128) sw1[i] = w1[i];
    for (int i = tid; i < CHID * COUT; i += 128) sw2[i] = w2[i];
    if (tid < CHID) sb1[tid] = b1[tid];
    if (tid < COUT) sb2[tid] = b2[tid];
    if (PREVNORM && tid >= 32 && tid < 64) {
        float z = warp_sum_partials(prevBS + (size_t)b * prevNB, prevNB, tid - 32);
        if (tid == 32) sZp = 1.f / z;
    }
    if (BASENORM && tid < 32) {
        float z = warp_sum_partials(baseBS + (size_t)b * baseNB, baseNB, tid);
        if (tid == 0) sZb = 1.f / z;
    }
    __syncthreads();

    const int N = Hout * Hout;
    const int n = blockIdx.x * 128 + tid;
    if (n >= N) return;
    const int oy = n / Hout, ox = n % Hout;

    int y0 = (oy - 1) >> 1; int y1v = y0 + 1;
    const float wy1 = (oy & 1) ? 0.25f : 0.75f; const float wy0 = 1.f - wy1;
    y0 = max(y0, 0); y1v = min(y1v, Hin - 1);
    int x0 = (ox - 1) >> 1; int x1v = x0 + 1;
    const float wx1 = (ox & 1) ? 0.25f : 0.75f; const float wx0 = 1.f - wx1;
    x0 = max(x0, 0); x1v = min(x1v, Hin - 1);

    const int Nin = Hin * Hin;
    const int p00 = y0 * Hin + x0,  p01 = y0 * Hin + x1v;
    const int p10 = y1v * Hin + x0, p11 = y1v * Hin + x1v;
    const float w00 = wy0 * wx0, w01 = wy0 * wx1, w10 = wy1 * wx0, w11 = wy1 * wx1;

    const float* q00 = prevO + ((size_t)b * Nin + p00) * CIN;
    const float* q01 = prevO + ((size_t)b * Nin + p01) * CIN;
    const float* q10 = prevO + ((size_t)b * Nin + p10) * CIN;
    const float* q11 = prevO + ((size_t)b * Nin + p11) * CIN;

    float fp = 0.f;
    const float* r00 = nullptr; const float* r01 = nullptr;
    const float* r10 = nullptr; const float* r11 = nullptr;
    if (PREVNORM) {
        fp = sZp;
        r00 = prevx1 + ((size_t)b * Nin + p00) * CIN;
        r01 = prevx1 + ((size_t)b * Nin + p01) * CIN;
        r10 = prevx1 + ((size_t)b * Nin + p10) * CIN;
        r11 = prevx1 + ((size_t)b * Nin + p11) * CIN;
    }
    const float* bO = nullptr; const float* bR = nullptr; float fb = 0.f;
    if (HASBASE) {
        bO = baseO + ((size_t)b * N + n) * CIN;
        if (BASENORM) {
            fb = sZb;
            bR = basex1 + ((size_t)b * N + n) * CIN;
        }
    }

    float hid[CHID];
#pragma unroll
    for (int j = 0; j < CHID; j++) hid[j] = sb1[j];

#pragma unroll
    for (int c = 0; c < CIN; c += 4) {
        float4 a00 = *reinterpret_cast<const float4*>(q00 + c);
        float4 a01 = *reinterpret_cast<const float4*>(q01 + c);
        float4 a10 = *reinterpret_cast<const float4*>(q10 + c);
        float4 a11 = *reinterpret_cast<const float4*>(q11 + c);
        if (PREVNORM) {
            float4 t;
            t = *reinterpret_cast<const float4*>(r00 + c);
            a00 = make_float4(a00.x*fp+t.x, a00.y*fp+t.y, a00.z*fp+t.z, a00.w*fp+t.w);
            t = *reinterpret_cast<const float4*>(r01 + c);
            a01 = make_float4(a01.x*fp+t.x, a01.y*fp+t.y, a01.z*fp+t.z, a01.w*fp+t.w);
            t = *reinterpret_cast<const float4*>(r10 + c);
            a10 = make_float4(a10.x*fp+t.x, a10.y*fp+t.y, a10.z*fp+t.z, a10.w*fp+t.w);
            t = *reinterpret_cast<const float4*>(r11 + c);
            a11 = make_float4(a11.x*fp+t.x, a11.y*fp+t.y, a11.z*fp+t.z, a11.w*fp+t.w);
        }
        float4 v = make_float4(0.f, 0.f, 0.f, 0.f);
        v = f4fma(a00, w00, v); v = f4fma(a01, w01, v);
        v = f4fma(a10, w10, v); v = f4fma(a11, w11, v);
        if (HASBASE) {
            float4 bb = *reinterpret_cast<const float4*>(bO + c);
#pragma unroll
            for (int s = 1; s < BNS; s++) {
                float4 b2 = *reinterpret_cast<const float4*>(bO + s * bosz + c);
                bb.x += b2.x; bb.y += b2.y; bb.z += b2.z; bb.w += b2.w;
            }
            if (BASENORM) {
                float4 t = *reinterpret_cast<const float4*>(bR + c);
                bb = make_float4(bb.x*fb+t.x, bb.y*fb+t.y, bb.z*fb+t.z, bb.w*fb+t.w);
            }
            v.x += bb.x; v.y += bb.y; v.z += bb.z; v.w += bb.w;
        }
        const float* wr = &sw1[c * CHID];
#pragma unroll
        for (int j = 0; j < CHID; j++)
            hid[j] += v.x * wr[j] + v.y * wr[CHID + j] + v.z * wr[2*CHID + j] + v.w * wr[3*CHID + j];
    }
#pragma unroll
    for (int j = 0; j < CHID; j++) hid[j] = fminf(fmaxf(hid[j], 0.f), 6.f);

    float accv[COUT];
#pragma unroll
    for (int k = 0; k < COUT; k++) accv[k] = sb2[k];
#pragma unroll
    for (int j = 0; j < CHID; j++) {
        const float hv = hid[j];
        const float* wr = &sw2[j * COUT];
#pragma unroll
        for (int k = 0; k < COUT; k++) accv[k] += hv * wr[k];
    }
    float* ob = out + ((size_t)b * N + n) * COUT;
#pragma unroll
    for (int k = 0; k < COUT; k++) ob[k] = accv[k];
}

// ============================================================================
// Launch
// ============================================================================
static inline int ceil_div(int a, int b) { return (a + b - 1) / b; }

template<int H, int RB, int C>
static inline int flash_smem_bytes() {
    constexpr int MB = 64, PH = H + 8, PM = MB + 8;
    int region = (C*RB + C*H) * 4;
    int mainr  = (2*MB*PH + 2*H*PM) * 2;
    if (mainr > region) region = mainr;
    return RB * PH * 2 + region;
}

extern "C" void kernel_launch(void* const* d_in, const int* in_sizes, int n_in,
                              void* d_out, int out_size)
{
    const float* f0 = (const float*)d_in[0];   // [2,160,14,14]
    const float* f1 = (const float*)d_in[1];   // [2,128,28,28]
    const float* f2 = (const float*)d_in[2];   // [2,64,56,56]
    const float* f3 = (const float*)d_in[3];   // [2,32,112,112]
    const float* cas1_w1 = (const float*)d_in[4];
    const float* cas1_w2 = (const float*)d_in[5];
    const float* cas2_w1 = (const float*)d_in[6];
    const float* cas2_w2 = (const float*)d_in[7];
    const float* cas3_w1 = (const float*)d_in[8];
    const float* cas3_w2 = (const float*)d_in[9];
    const float* m1w1 = (const float*)d_in[10]; const float* m1b1 = (const float*)d_in[11];
    const float* m1w2 = (const float*)d_in[12]; const float* m1b2 = (const float*)d_in[13];
    const float* m2w1 = (const float*)d_in[14]; const float* m2b1 = (const float*)d_in[15];
    const float* m2w2 = (const float*)d_in[16]; const float* m2b2 = (const float*)d_in[17];
    const float* m3w1 = (const float*)d_in[18]; const float* m3b1 = (const float*)d_in[19];
    const float* m3w2 = (const float*)d_in[20]; const float* m3b2 = (const float*)d_in[21];
    const float* m4w1 = (const float*)d_in[22]; const float* m4b1 = (const float*)d_in[23];
    const float* m4w2 = (const float*)d_in[24]; const float* m4b2 = (const float*)d_in[25];
    float* outp = (float*)d_out;

    float* S = nullptr;
    cudaGetSymbolAddress((void**)&S, g_scratch);
    __nv_bfloat16* B = nullptr;
    cudaGetSymbolAddress((void**)&B, g_bf);

    float* x1a = S + OFF_X1A; float* Oa = S + OFF_OA;
    float* x1b = S + OFF_X1B; float* Ob = S + OFF_OB;   // 4 split partials
    float* x1c = S + OFF_X1C; float* Oc = S + OFF_OC;   // 4 split partials
    float* y1 = S + OFF_Y1; float* y2 = S + OFF_Y2; float* y3 = S + OFF_Y3;
    float* BSa = S + OFF_BSA; float* BSb = S + OFF_BSB; float* BSc = S + OFF_BSC;

    __nv_bfloat16* x2abf = B + BOFF_X2A; __nv_bfloat16* x2aT = B + BOFF_TA;
    __nv_bfloat16* x2bbf = B + BOFF_X2B; __nv_bfloat16* x2bT = B + BOFF_TB;
    __nv_bfloat16* x2cbf = B + BOFF_X2C; __nv_bfloat16* x2cT = B + BOFF_TC;

    const int NBA = 832/64;      // 13 blocks, NS=1
    const int NBB = 3136/64;     // 49 blocks, NS=4
    const int NBC = 12544/128;   // 98 blocks, NS=4

    const int smemA = flash_smem_bytes<64,64,128>();
    const int smemB = flash_smem_bytes<64,64,64>();
    const int smemC = flash_smem_bytes<32,128,32>();
    cudaFuncSetAttribute((const void*)flash_fused_kernel<64,64,128>,
                         cudaFuncAttributeMaxDynamicSharedMemorySize, smemA);
    cudaFuncSetAttribute((const void*)flash_fused_kernel<64,64,64>,
                         cudaFuncAttributeMaxDynamicSharedMemorySize, smemB);
    cudaFuncSetAttribute((const void*)flash_fused_kernel<32,128,32>,
                         cudaFuncAttributeMaxDynamicSharedMemorySize, smemC);

    // ---------------- CSA1: N1=784 (p832), N2=196 (p256), H=64, NS=1
    proj_plain_kernel<160,64><<<dim3(ceil_div(256,32),2), 256>>>(
        f0, cas1_w2, x2abf, x2aT, 196, 256, (size_t)160*196);
    flash_fused_kernel<64,64,128><<<dim3(NBA,2,1), 128, smemA>>>(
        f1, cas1_w1, x2abf, x2aT, x1a, Oa, BSa, 784, 196, 256);

    // ---------------- CSA2: N1=3136, N2=784 (p832), H=64, NS=4
    proj_norm_kernel<64,64,1><<<dim3(ceil_div(832,16),2), 512>>>(
        Oa, 0, x1a, BSa, NBA, cas2_w2, x2bbf, x2bT, 784, 832);
    flash_fused_kernel<64,64,64><<<dim3(NBB,2,4), 128, smemB>>>(
        f2, cas2_w1, x2bbf, x2bT, x1b, Ob, BSb, 3136, 784, 832);

    // ---------------- CSA3: N1=12544, N2=3136, H=32, NS=4
    proj_norm_kernel<64,32,4><<<dim3(ceil_div(3136,16),2), 512>>>(
        Ob, OSZ_B, x1b, BSb, 4*NBB, cas3_w2, x2cbf, x2cT, 3136, 3136);
    flash_fused_kernel<32,128,32><<<dim3(NBC,2,4), 256, smemC>>>(
        f3, cas3_w1, x2cbf, x2cT, x1c, Oc, BSc, 12544, 3136, 3136);

    // ---------------- decoder (softmax-normalization folded in)
    msr_kernel<64,64,32,true,true,true,4><<<dim3(ceil_div(3136,128),2), 128>>>(
        Ob, OSZ_B, x1b, BSb, 4*NBB, Oa, x1a, BSa, NBA,
        m1w1, m1b1, m1w2, m1b2, y1, 56, 28);
    msr_kernel<32,32,16,true,false,true,4><<<dim3(ceil_div(12544,128),2), 128>>>(
        Oc, OSZ_C, x1c, BSc, 4*NBC, y1, nullptr, nullptr, 0,
        m2w1, m2b1, m2w2, m2b2, y2, 112, 56);
    msr_kernel<16,16,8,false,false,false,1><<<dim3(ceil_div(50176,128),2), 128>>>(
        nullptr, 0, nullptr, nullptr, 0, y2, nullptr, nullptr, 0,
        m3w1, m3b1, m3w2, m3b2, y3, 224, 112);
    msr_kernel<8,2,1,false,false,false,1><<<dim3(ceil_div(200704,128),2), 128>>>(
        nullptr, 0, nullptr, nullptr, 0, y3, nullptr, nullptr, 0,
        m4w1, m4b1, m4w2, m4b2, outp, 448, 224);

    (void)in_sizes; (void)n_in; (void)out_size;
}

// round 14
// speedup vs baseline: 1.0467x; 1.0467x over previous
#include <cuda_runtime.h>
#include <cuda_bf16.h>
#include <math.h>
#include <stdint.h>

// ============================================================================
// fp32 scratch  (Ob/Oc have 4 k-split partial buffers)
// ============================================================================
static constexpr size_t OSZ_B = (size_t)2*3136*64;    // one split buffer
static constexpr size_t OSZ_C = (size_t)2*12544*32;

static constexpr size_t SZ_X1A = (size_t)2*784*64;
static constexpr size_t SZ_OA  = (size_t)2*784*64;
static constexpr size_t SZ_X1B = (size_t)2*3136*64;
static constexpr size_t SZ_OB  = 4*OSZ_B;
static constexpr size_t SZ_X1C = (size_t)2*12544*32;
static constexpr size_t SZ_OC  = 4*OSZ_C;
static constexpr size_t SZ_Y1  = (size_t)2*3136*32;
static constexpr size_t SZ_Y2  = (size_t)2*12544*16;
static constexpr size_t SZ_Y3  = (size_t)2*50176*8;
static constexpr size_t SZ_BS  = (size_t)2*512;

static constexpr size_t OFF_X1A = 0;
static constexpr size_t OFF_OA  = OFF_X1A + SZ_X1A;
static constexpr size_t OFF_X1B = OFF_OA  + SZ_OA;
static constexpr size_t OFF_OB  = OFF_X1B + SZ_X1B;
static constexpr size_t OFF_X1C = OFF_OB  + SZ_OB;
static constexpr size_t OFF_OC  = OFF_X1C + SZ_X1C;
static constexpr size_t OFF_Y1  = OFF_OC  + SZ_OC;
static constexpr size_t OFF_Y2  = OFF_Y1  + SZ_Y1;
static constexpr size_t OFF_Y3  = OFF_Y2  + SZ_Y2;
static constexpr size_t OFF_BSA = OFF_Y3  + SZ_Y3;
static constexpr size_t OFF_BSB = OFF_BSA + SZ_BS;
static constexpr size_t OFF_BSC = OFF_BSB + SZ_BS;
static constexpr size_t SCRATCH_TOTAL = OFF_BSC + SZ_BS;
__device__ __align__(16) float g_scratch[SCRATCH_TOTAL];

// ============================================================================
// bf16 scratch: x1bf + x2 row-major + x2 transposed per stage (pads zeroed)
// ============================================================================
static constexpr size_t BOFF_X1A = 0;                                   // 2*832*64
static constexpr size_t BOFF_X2A = BOFF_X1A + (size_t)2*832*64;         // 2*256*64
static constexpr size_t BOFF_TA  = BOFF_X2A + (size_t)2*256*64;         // 2*64*256
static constexpr size_t BOFF_X1B = BOFF_TA  + (size_t)2*64*256;         // 2*3136*64
static constexpr size_t BOFF_X2B = BOFF_X1B + (size_t)2*3136*64;        // 2*832*64
static constexpr size_t BOFF_TB  = BOFF_X2B + (size_t)2*832*64;         // 2*64*832
static constexpr size_t BOFF_X1C = BOFF_TB  + (size_t)2*64*832;         // 2*12544*32
static constexpr size_t BOFF_X2C = BOFF_X1C + (size_t)2*12544*32;       // 2*3136*32
static constexpr size_t BOFF_TC  = BOFF_X2C + (size_t)2*3136*32;        // 2*32*3136
static constexpr size_t BSCRATCH_TOTAL = BOFF_TC + (size_t)2*32*3136;
__device__ __align__(16) __nv_bfloat16 g_bf[BSCRATCH_TOTAL];

#define MMA_BF16(d, a, b)                                                      \
    asm volatile(                                                              \
        "mma.sync.aligned.m16n8k16.row.col.f32.bf16.bf16.f32 "                 \
        "{%0,%1,%2,%3},{%4,%5,%6,%7},{%8,%9},{%0,%1,%2,%3};"                   \
        : "+f"((d)[0]), "+f"((d)[1]), "+f"((d)[2]), "+f"((d)[3])               \
        : "r"((a)[0]), "r"((a)[1]), "r"((a)[2]), "r"((a)[3]),                  \
          "r"((b)[0]), "r"((b)[1]))

__device__ __forceinline__ void cp16(uint32_t saddr, const void* gptr) {
    asm volatile("cp.async.ca.shared.global [%0], [%1], 16;" :: "r"(saddr), "l"(gptr));
}
__device__ __forceinline__ uint32_t pack_bf2(float lo, float hi) {
    __nv_bfloat162 v = __floats2bfloat162_rn(lo, hi);
    return *reinterpret_cast<uint32_t*>(&v);
}

// Warp-0 deterministic partial-sum (identical everywhere -> identical Z).
__device__ __forceinline__ float warp_sum_partials(const float* bs, int NB, int lane) {
    float z = 0.f;
    for (int i = lane; i < NB; i += 32) z += bs[i];
#pragma unroll
    for (int off = 16; off > 0; off >>= 1)
        z += __shfl_xor_sync(0xffffffffu, z, off);
    return z;
}

// ============================================================================
// Plain projection (NCHW source, coalesced): X2 for CSA1 (bf16 + transpose).
// ============================================================================
template<int C, int H>
__global__ void __launch_bounds__(256) proj_plain_kernel(
    const float* __restrict__ X, const float* __restrict__ W,
    __nv_bfloat16* __restrict__ outbf, __nv_bfloat16* __restrict__ outT,
    int N, int Np, size_t bstride)
{
    __shared__ float sw[C*H];
    const int tid = threadIdx.x;
    for (int i = tid; i < C*H; i += 256) sw[i] = W[i];
    __syncthreads();
    const int b = blockIdx.y;
    const int n = blockIdx.x * 32 + (tid & 31);
    const int ty = tid >> 5;
    constexpr int HP = H / 8;
    if (n >= Np) return;

    float acc[HP];
#pragma unroll
    for (int k = 0; k < HP; k++) acc[k] = 0.f;
    if (n < N) {
        const float* xb = X + (size_t)b * bstride;
        for (int c = 0; c < C; c++) {
            float v = xb[(size_t)c * N + n];
            const float* wr = &sw[c*H + ty*HP];
#pragma unroll
            for (int k = 0; k < HP; k++) acc[k] += v * wr[k];
        }
    }
    __nv_bfloat16* obf = outbf + ((size_t)b * Np + n) * H + ty * HP;
#pragma unroll
    for (int k = 0; k < HP; k += 2)
        *reinterpret_cast<uint32_t*>(obf + k) = pack_bf2(acc[k], acc[k+1]);
    __nv_bfloat16* ot = outT + (size_t)b * H * Np;
#pragma unroll
    for (int k = 0; k < HP; k++) ot[(size_t)(ty * HP + k) * Np + n] = __float2bfloat16(acc[k]);
}

// ============================================================================
// X1 projection (NCHW source, coalesced): bf16 [Np][H] + fp32 residual [N][H].
// ============================================================================
template<int C, int H>
__global__ void __launch_bounds__(256) proj_x1_kernel(
    const float* __restrict__ X, const float* __restrict__ W,
    float* __restrict__ out32, __nv_bfloat16* __restrict__ outbf,
    int N, int Np, size_t bstride)
{
    __shared__ float sw[C*H];
    const int tid = threadIdx.x;
    for (int i = tid; i < C*H; i += 256) sw[i] = W[i];
    __syncthreads();
    const int b = blockIdx.y;
    const int n = blockIdx.x * 32 + (tid & 31);
    const int ty = tid >> 5;
    constexpr int HP = H / 8;
    if (n >= Np) return;

    float acc[HP];
#pragma unroll
    for (int k = 0; k < HP; k++) acc[k] = 0.f;
    if (n < N) {
        const float* xb = X + (size_t)b * bstride;
        for (int c = 0; c < C; c++) {
            float v = xb[(size_t)c * N + n];
            const float* wr = &sw[c*H + ty*HP];
#pragma unroll
            for (int k = 0; k < HP; k++) acc[k] += v * wr[k];
        }
    }
    __nv_bfloat16* obf = outbf + ((size_t)b * Np + n) * H + ty * HP;
#pragma unroll
    for (int k = 0; k < HP; k += 2)
        *reinterpret_cast<uint32_t*>(obf + k) = pack_bf2(acc[k], acc[k+1]);
    if (n < N) {
        float* o32 = out32 + ((size_t)b * N + n) * H + ty * HP;
#pragma unroll
        for (int k = 0; k < HP; k += 4)
            *reinterpret_cast<float4*>(o32 + k) = make_float4(acc[k], acc[k+1], acc[k+2], acc[k+3]);
    }
}

// ============================================================================
// Norm-folded projection: In(n,c) = (sum_s O_s)(n,c)/Z + xres(n,c), out = In.W
// 512 threads: 16 px x 16 hg x 2 C-halves. Z from per-block partials.
// ============================================================================
template<int C, int H, int NSPLIT>
__global__ void __launch_bounds__(512) proj_norm_kernel(
    const float* __restrict__ O, size_t osz,
    const float* __restrict__ xres,
    const float* __restrict__ BS, int NB,
    const float* __restrict__ W,
    __nv_bfloat16* __restrict__ outbf, __nv_bfloat16* __restrict__ outT,
    int N, int Np)
{
    constexpr int PXB = 16;
    constexpr int PPX = PXB + 1;
    constexpr int HP  = H / 16;
    __shared__ float sraw[C * PPX];
    __shared__ float sw[C * H];
    __shared__ float sacc[PXB * 16 * HP];
    __shared__ float sZ;
    const int tid = threadIdx.x;
    const int b = blockIdx.y;
    const int px0 = blockIdx.x * PXB;
    for (int i = tid; i < C*H; i += 512) sw[i] = W[i];
    if (tid < 32) {
        float z = warp_sum_partials(BS + (size_t)b * NB, NB, tid);
        if (tid == 0) sZ = 1.f / z;
    }
    __syncthreads();

    const float f = sZ;
    constexpr int C4 = C / 4;
    for (int i = tid; i < PXB * C4; i += 512) {
        int c4 = i % C4, px = i / C4;
        int n = px0 + px;
        float4 o4 = make_float4(0.f,0.f,0.f,0.f), r4 = o4;
        if (n < N) {
            size_t idx = ((size_t)b * N + n) * C + c4 * 4;
            o4 = *reinterpret_cast<const float4*>(O + idx);
#pragma unroll
            for (int s = 1; s < NSPLIT; s++) {
                float4 t = *reinterpret_cast<const float4*>(O + s * osz + idx);
                o4.x += t.x; o4.y += t.y; o4.z += t.z; o4.w += t.w;
            }
            r4 = *reinterpret_cast<const float4*>(xres + idx);
        }
        sraw[(c4*4+0) * PPX + px] = o4.x * f + r4.x;
        sraw[(c4*4+1) * PPX + px] = o4.y * f + r4.y;
        sraw[(c4*4+2) * PPX + px] = o4.z * f + r4.z;
        sraw[(c4*4+3) * PPX + px] = o4.w * f + r4.w;
    }
    __syncthreads();

    const int ch = tid >> 8;
    const int px = tid & (PXB - 1);
    const int hg = (tid >> 4) & 15;
    float acc[HP];
#pragma unroll
    for (int k = 0; k < HP; k++) acc[k] = 0.f;
#pragma unroll 4
    for (int c = ch * (C/2); c < (ch + 1) * (C/2); c++) {
        float v = sraw[c * PPX + px];
        if (HP == 4) {
            float4 w4 = *reinterpret_cast<const float4*>(&sw[c*H + hg*4]);
            acc[0] += v * w4.x; acc[1] += v * w4.y;
            acc[2] += v * w4.z; acc[3] += v * w4.w;
        } else {
            float2 w2 = *reinterpret_cast<const float2*>(&sw[c*H + hg*2]);
            acc[0] += v * w2.x; acc[1] += v * w2.y;
        }
    }
    if (ch == 1) {
#pragma unroll
        for (int k = 0; k < HP; k++) sacc[(hg * PXB + px) * HP + k] = acc[k];
    }
    __syncthreads();
    if (ch != 0) return;
    const int n = px0 + px;
    if (n >= Np) return;
#pragma unroll
    for (int k = 0; k < HP; k++) acc[k] += sacc[(hg * PXB + px) * HP + k];

    __nv_bfloat16* obf = outbf + ((size_t)b * Np + n) * H + hg * HP;
#pragma unroll
    for (int k = 0; k < HP; k += 2)
        *reinterpret_cast<uint32_t*>(obf + k) = pack_bf2(acc[k], acc[k+1]);
    __nv_bfloat16* ot = outT + (size_t)b * H * Np;
#pragma unroll
    for (int k = 0; k < HP; k++) ot[(size_t)(hg * HP + k) * Np + n] = __float2bfloat16(acc[k]);
}

// ============================================================================
// FA2-style bf16 flash CSA, X1 from precomputed bf16 (no fused proj),
// no max stabilization, N2 k-split across blocks (blockIdx.z).
// ============================================================================
template<int H, int RB>
__global__ void __launch_bounds__(RB*2) flash_kernel(
    const __nv_bfloat16* __restrict__ X1bf,   // [b][N1p][H]
    const __nv_bfloat16* __restrict__ X2bf,   // [b][N2p][H]
    const __nv_bfloat16* __restrict__ X2T,    // [b][H][N2p]
    float* __restrict__ Oout, float* __restrict__ blocksum,
    int N1, int N2, int N1p, int N2p)
{
    constexpr int THREADS = RB * 2;
    constexpr int MB = 64;
    constexpr int PH = H + 8;
    constexpr int PM = MB + 8;
    constexpr int KSQ = H / 16;
    constexpr int NTS = MB / 8;
    constexpr int KSA = MB / 16;
    constexpr int NTO = H / 8;
    constexpr int CPR = H * 2 / 16;

    extern __shared__ __nv_bfloat16 smh[];
    __nv_bfloat16* sX1 = smh;                    // RB*PH
    __nv_bfloat16* sX2 = sX1 + RB*PH;            // 2*MB*PH
    __nv_bfloat16* sT  = sX2 + 2*MB*PH;          // 2*H*PM

    const int b = blockIdx.y;
    const int split = blockIdx.z;
    const int NS = gridDim.z;
    const int row0 = blockIdx.x * RB;
    const int tid = threadIdx.x, w = tid >> 5, lane = tid & 31;
    const int g = lane >> 2, t4 = lane & 3;
    const int wrow = w * 16;

    float* Op = Oout + (size_t)split * 2 * N1 * H;

    // ---- load X1 tile (bf16, padded rows already zeroed by proj)
    const __nv_bfloat16* x1 = X1bf + (size_t)b * N1p * H;
    for (int c = tid; c < RB * CPR; c += THREADS) {
        int r = c / CPR, k = c % CPR;
        uint4 v = *reinterpret_cast<const uint4*>(x1 + (size_t)(row0 + r) * H + k * 8);
        *reinterpret_cast<uint4*>(sX1 + r * PH + k * 8) = v;
    }

    const __nv_bfloat16* x2 = X2bf + (size_t)b * N2p * H;
    const __nv_bfloat16* xt = X2T  + (size_t)b * H * N2p;
    const int T = (N2 + MB - 1) / MB;
    const int t0 = (T * split) / NS;
    const int t1 = (T * (split + 1)) / NS;

    auto prefetch = [&](int t) {
        int buf = t & 1;
        uint32_t d2 = (uint32_t)__cvta_generic_to_shared(sX2 + buf * MB * PH);
        const __nv_bfloat16* src = x2 + (size_t)t * MB * H;
        for (int c = tid; c < MB * CPR; c += THREADS) {
            int r = c / CPR, k = c % CPR;
            cp16(d2 + (r * PH + k * 8) * 2, src + (size_t)r * H + k * 8);
        }
        uint32_t dT = (uint32_t)__cvta_generic_to_shared(sT + buf * H * PM);
        for (int c = tid; c < H * 8; c += THREADS) {
            int r = c / 8, k = c % 8;
            cp16(dT + (r * PM + k * 8) * 2, xt + (size_t)r * N2p + (size_t)t * MB + k * 8);
        }
        asm volatile("cp.async.commit_group;");
    };

    prefetch(t0);

    float s0 = 0.f, s1 = 0.f;
    float o[NTO][4];
#pragma unroll
    for (int nt = 0; nt < NTO; nt++)
#pragma unroll
        for (int k = 0; k < 4; k++) o[nt][k] = 0.f;

    for (int t = t0; t < t1; t++) {
        asm volatile("cp.async.wait_group 0;");
        __syncthreads();
        if (t + 1 < t1) prefetch(t + 1);
        const __nv_bfloat16* bX2 = sX2 + (t & 1) * MB * PH;
        const __nv_bfloat16* bT  = sT  + (t & 1) * H * PM;

        float sacc[NTS][4];
#pragma unroll
        for (int nt = 0; nt < NTS; nt++)
#pragma unroll
            for (int k = 0; k < 4; k++) sacc[nt][k] = 0.f;
#pragma unroll
        for (int ks = 0; ks < KSQ; ks++) {
            const int cb = ks * 16 + 2 * t4;
            uint32_t a[4];
            a[0] = *reinterpret_cast<const uint32_t*>(sX1 + (wrow + g) * PH + cb);
            a[1] = *reinterpret_cast<const uint32_t*>(sX1 + (wrow + g + 8) * PH + cb);
            a[2] = *reinterpret_cast<const uint32_t*>(sX1 + (wrow + g) * PH + cb + 8);
            a[3] = *reinterpret_cast<const uint32_t*>(sX1 + (wrow + g + 8) * PH + cb + 8);
#pragma unroll
            for (int nt = 0; nt < NTS; nt++) {
                uint32_t bb[2];
                bb[0] = *reinterpret_cast<const uint32_t*>(bX2 + (nt * 8 + g) * PH + cb);
                bb[1] = *reinterpret_cast<const uint32_t*>(bX2 + (nt * 8 + g) * PH + cb + 8);
                MMA_BF16(sacc[nt], a, bb);
            }
        }

        const int limit = N2 - t * MB;
        const bool full = (limit >= MB);

        // ---- P = exp(S) directly (scores bounded, no max needed)
        uint32_t pA[KSA][4];
#pragma unroll
        for (int nt = 0; nt < NTS; nt++) {
            int c0 = nt * 8 + 2 * t4;
            float p0 = (full || c0     < limit) ? __expf(sacc[nt][0]) : 0.f;
            float p1 = (full || c0 + 1 < limit) ? __expf(sacc[nt][1]) : 0.f;
            float p2 = (full || c0     < limit) ? __expf(sacc[nt][2]) : 0.f;
            float p3 = (full || c0 + 1 < limit) ? __expf(sacc[nt][3]) : 0.f;
            s0 += p0 + p1; s1 += p2 + p3;
            pA[nt >> 1][(nt & 1) * 2 + 0] = pack_bf2(p0, p1);
            pA[nt >> 1][(nt & 1) * 2 + 1] = pack_bf2(p2, p3);
        }

        // ---- O += P . X2
#pragma unroll
        for (int ks = 0; ks < KSA; ks++) {
#pragma unroll
            for (int nt = 0; nt < NTO; nt++) {
                const int rb2 = (nt * 8 + g) * PM + ks * 16 + 2 * t4;
                uint32_t bb[2];
                bb[0] = *reinterpret_cast<const uint32_t*>(bT + rb2);
                bb[1] = *reinterpret_cast<const uint32_t*>(bT + rb2 + 8);
                MMA_BF16(o[nt], pA[ks], bb);
            }
        }
    }

    // ---- final row-sum reduce over t4 quad
    s0 += __shfl_xor_sync(0xffffffffu, s0, 1);
    s0 += __shfl_xor_sync(0xffffffffu, s0, 2);
    s1 += __shfl_xor_sync(0xffffffffu, s1, 1);
    s1 += __shfl_xor_sync(0xffffffffu, s1, 2);

    const int gr0 = row0 + wrow + g;
    const int gr1 = gr0 + 8;
    {
        if (gr0 < N1) {
            float* dst = Op + ((size_t)b * N1 + gr0) * H;
#pragma unroll
            for (int nt = 0; nt < NTO; nt++)
                *reinterpret_cast<float2*>(dst + nt * 8 + 2 * t4) = make_float2(o[nt][0], o[nt][1]);
        }
        if (gr1 < N1) {
            float* dst = Op + ((size_t)b * N1 + gr1) * H;
#pragma unroll
            for (int nt = 0; nt < NTO; nt++)
                *reinterpret_cast<float2*>(dst + nt * 8 + 2 * t4) = make_float2(o[nt][2], o[nt][3]);
        }
    }

    // ---- per-block deterministic Z partial (padded rows masked to 0)
    __syncthreads();
    float* sRS = (float*)smh;
    if (t4 == 0) {
        sRS[wrow + g]     = (gr0 < N1) ? s0 : 0.f;
        sRS[wrow + g + 8] = (gr1 < N1) ? s1 : 0.f;
    }
    __syncthreads();
    if (tid == 0) {
        float z = 0.f;
        for (int r = 0; r < RB; r++) z += sRS[r];
        blocksum[((size_t)b * NS + split) * gridDim.x + blockIdx.x] = z;
    }
}

// ============================================================================
// MSR with optional folded softmax-normalization (Z from block partials).
// BNS: number of base O k-split partials to sum.
// ============================================================================
__device__ __forceinline__ float4 f4fma(float4 a, float s, float4 acc) {
    acc.x += a.x * s; acc.y += a.y * s; acc.z += a.z * s; acc.w += a.w * s;
    return acc;
}

template<int CIN, int CHID, int COUT, bool HASBASE, bool PREVNORM, bool BASENORM, int BNS>
__global__ void __launch_bounds__(128) msr_kernel(
    const float* __restrict__ baseO, size_t bosz,
    const float* __restrict__ basex1,
    const float* __restrict__ baseBS, int baseNB,
    const float* __restrict__ prevO, const float* __restrict__ prevx1,
    const float* __restrict__ prevBS, int prevNB,
    const float* __restrict__ w1, const float* __restrict__ b1,
    const float* __restrict__ w2, const float* __restrict__ b2,
    float* __restrict__ out, int Hout, int Hin)
{
    __shared__ float sw1[CIN * CHID];
    __shared__ float sw2[CHID * COUT];
    __shared__ float sb1[CHID];
    __shared__ float sb2[COUT];
    __shared__ float sZp, sZb;
    const int tid = threadIdx.x;
    const int b = blockIdx.y;
    for (int i = tid; i < CIN * CHID; i += 128) sw1[i] = w1[i];
    for (int i = tid; i < CHID * COUT; i += 128) sw2[i] = w2[i];
    if (tid < CHID) sb1[tid] = b1[tid];
    if (tid < COUT) sb2[tid] = b2[tid];
    if (PREVNORM && tid >= 32 && tid < 64) {
        float z = warp_sum_partials(prevBS + (size_t)b * prevNB, prevNB, tid - 32);
        if (tid == 32) sZp = 1.f / z;
    }
    if (BASENORM && tid < 32) {
        float z = warp_sum_partials(baseBS + (size_t)b * baseNB, baseNB, tid);
        if (tid == 0) sZb = 1.f / z;
    }
    __syncthreads();

    const int N = Hout * Hout;
    const int n = blockIdx.x * 128 + tid;
    if (n >= N) return;
    const int oy = n / Hout, ox = n % Hout;

    int y0 = (oy - 1) >> 1; int y1v = y0 + 1;
    const float wy1 = (oy & 1) ? 0.25f : 0.75f; const float wy0 = 1.f - wy1;
    y0 = max(y0, 0); y1v = min(y1v, Hin - 1);
    int x0 = (ox - 1) >> 1; int x1v = x0 + 1;
    const float wx1 = (ox & 1) ? 0.25f : 0.75f; const float wx0 = 1.f - wx1;
    x0 = max(x0, 0); x1v = min(x1v, Hin - 1);

    const int Nin = Hin * Hin;
    const int p00 = y0 * Hin + x0,  p01 = y0 * Hin + x1v;
    const int p10 = y1v * Hin + x0, p11 = y1v * Hin + x1v;
    const float w00 = wy0 * wx0, w01 = wy0 * wx1, w10 = wy1 * wx0, w11 = wy1 * wx1;

    const float* q00 = prevO + ((size_t)b * Nin + p00) * CIN;
    const float* q01 = prevO + ((size_t)b * Nin + p01) * CIN;
    const float* q10 = prevO + ((size_t)b * Nin + p10) * CIN;
    const float* q11 = prevO + ((size_t)b * Nin + p11) * CIN;

    float fp = 0.f;
    const float* r00 = nullptr; const float* r01 = nullptr;
    const float* r10 = nullptr; const float* r11 = nullptr;
    if (PREVNORM) {
        fp = sZp;
        r00 = prevx1 + ((size_t)b * Nin + p00) * CIN;
        r01 = prevx1 + ((size_t)b * Nin + p01) * CIN;
        r10 = prevx1 + ((size_t)b * Nin + p10) * CIN;
        r11 = prevx1 + ((size_t)b * Nin + p11) * CIN;
    }
    const float* bO = nullptr; const float* bR = nullptr; float fb = 0.f;
    if (HASBASE) {
        bO = baseO + ((size_t)b * N + n) * CIN;
        if (BASENORM) {
            fb = sZb;
            bR = basex1 + ((size_t)b * N + n) * CIN;
        }
    }

    float hid[CHID];
#pragma unroll
    for (int j = 0; j < CHID; j++) hid[j] = sb1[j];

#pragma unroll
    for (int c = 0; c < CIN; c += 4) {
        float4 a00 = *reinterpret_cast<const float4*>(q00 + c);
        float4 a01 = *reinterpret_cast<const float4*>(q01 + c);
        float4 a10 = *reinterpret_cast<const float4*>(q10 + c);
        float4 a11 = *reinterpret_cast<const float4*>(q11 + c);
        if (PREVNORM) {
            float4 t;
            t = *reinterpret_cast<const float4*>(r00 + c);
            a00 = make_float4(a00.x*fp+t.x, a00.y*fp+t.y, a00.z*fp+t.z, a00.w*fp+t.w);
            t = *reinterpret_cast<const float4*>(r01 + c);
            a01 = make_float4(a01.x*fp+t.x, a01.y*fp+t.y, a01.z*fp+t.z, a01.w*fp+t.w);
            t = *reinterpret_cast<const float4*>(r10 + c);
            a10 = make_float4(a10.x*fp+t.x, a10.y*fp+t.y, a10.z*fp+t.z, a10.w*fp+t.w);
            t = *reinterpret_cast<const float4*>(r11 + c);
            a11 = make_float4(a11.x*fp+t.x, a11.y*fp+t.y, a11.z*fp+t.z, a11.w*fp+t.w);
        }
        float4 v = make_float4(0.f, 0.f, 0.f, 0.f);
        v = f4fma(a00, w00, v); v = f4fma(a01, w01, v);
        v = f4fma(a10, w10, v); v = f4fma(a11, w11, v);
        if (HASBASE) {
            float4 bb = *reinterpret_cast<const float4*>(bO + c);
#pragma unroll
            for (int s = 1; s < BNS; s++) {
                float4 b2 = *reinterpret_cast<const float4*>(bO + s * bosz + c);
                bb.x += b2.x; bb.y += b2.y; bb.z += b2.z; bb.w += b2.w;
            }
            if (BASENORM) {
                float4 t = *reinterpret_cast<const float4*>(bR + c);
                bb = make_float4(bb.x*fb+t.x, bb.y*fb+t.y, bb.z*fb+t.z, bb.w*fb+t.w);
            }
            v.x += bb.x; v.y += bb.y; v.z += bb.z; v.w += bb.w;
        }
        const float* wr = &sw1[c * CHID];
#pragma unroll
        for (int j = 0; j < CHID; j++)
            hid[j] += v.x * wr[j] + v.y * wr[CHID + j] + v.z * wr[2*CHID + j] + v.w * wr[3*CHID + j];
    }
#pragma unroll
    for (int j = 0; j < CHID; j++) hid[j] = fminf(fmaxf(hid[j], 0.f), 6.f);

    float accv[COUT];
#pragma unroll
    for (int k = 0; k < COUT; k++) accv[k] = sb2[k];
#pragma unroll
    for (int j = 0; j < CHID; j++) {
        const float hv = hid[j];
        const float* wr = &sw2[j * COUT];
#pragma unroll
        for (int k = 0; k < COUT; k++) accv[k] += hv * wr[k];
    }
    float* ob = out + ((size_t)b * N + n) * COUT;
#pragma unroll
    for (int k = 0; k < COUT; k++) ob[k] = accv[k];
}

// ============================================================================
// Launch
// ============================================================================
static inline int ceil_div(int a, int b) { return (a + b - 1) / b; }

template<int H, int RB>
static inline int flash_smem_bytes() {
    constexpr int MB = 64, PH = H + 8, PM = MB + 8;
    return (RB*PH + 2*MB*PH + 2*H*PM) * 2;
}

extern "C" void kernel_launch(void* const* d_in, const int* in_sizes, int n_in,
                              void* d_out, int out_size)
{
    const float* f0 = (const float*)d_in[0];   // [2,160,14,14]
    const float* f1 = (const float*)d_in[1];   // [2,128,28,28]
    const float* f2 = (const float*)d_in[2];   // [2,64,56,56]
    const float* f3 = (const float*)d_in[3];   // [2,32,112,112]
    const float* cas1_w1 = (const float*)d_in[4];
    const float* cas1_w2 = (const float*)d_in[5];
    const float* cas2_w1 = (const float*)d_in[6];
    const float* cas2_w2 = (const float*)d_in[7];
    const float* cas3_w1 = (const float*)d_in[8];
    const float* cas3_w2 = (const float*)d_in[9];
    const float* m1w1 = (const float*)d_in[10]; const float* m1b1 = (const float*)d_in[11];
    const float* m1w2 = (const float*)d_in[12]; const float* m1b2 = (const float*)d_in[13];
    const float* m2w1 = (const float*)d_in[14]; const float* m2b1 = (const float*)d_in[15];
    const float* m2w2 = (const float*)d_in[16]; const float* m2b2 = (const float*)d_in[17];
    const float* m3w1 = (const float*)d_in[18]; const float* m3b1 = (const float*)d_in[19];
    const float* m3w2 = (const float*)d_in[20]; const float* m3b2 = (const float*)d_in[21];
    const float* m4w1 = (const float*)d_in[22]; const float* m4b1 = (const float*)d_in[23];
    const float* m4w2 = (const float*)d_in[24]; const float* m4b2 = (const float*)d_in[25];
    float* outp = (float*)d_out;

    float* S = nullptr;
    cudaGetSymbolAddress((void**)&S, g_scratch);
    __nv_bfloat16* B = nullptr;
    cudaGetSymbolAddress((void**)&B, g_bf);

    float* x1a = S + OFF_X1A; float* Oa = S + OFF_OA;
    float* x1b = S + OFF_X1B; float* Ob = S + OFF_OB;
    float* x1c = S + OFF_X1C; float* Oc = S + OFF_OC;
    float* y1 = S + OFF_Y1; float* y2 = S + OFF_Y2; float* y3 = S + OFF_Y3;
    float* BSa = S + OFF_BSA; float* BSb = S + OFF_BSB; float* BSc = S + OFF_BSC;

    __nv_bfloat16* x1abf = B + BOFF_X1A;
    __nv_bfloat16* x2abf = B + BOFF_X2A; __nv_bfloat16* x2aT = B + BOFF_TA;
    __nv_bfloat16* x1bbf = B + BOFF_X1B;
    __nv_bfloat16* x2bbf = B + BOFF_X2B; __nv_bfloat16* x2bT = B + BOFF_TB;
    __nv_bfloat16* x1cbf = B + BOFF_X1C;
    __nv_bfloat16* x2cbf = B + BOFF_X2C; __nv_bfloat16* x2cT = B + BOFF_TC;

    const int NBA = 832/64;      // 13 blocks, NS=1
    const int NBB = 3136/64;     // 49 blocks, NS=4
    const int NBC = 12544/128;   // 98 blocks, NS=4

    const int smemA = flash_smem_bytes<64,64>();   // 46080
    const int smemC = flash_smem_bytes<32,128>();  // 29696
    cudaFuncSetAttribute((const void*)flash_kernel<64,64>,
                         cudaFuncAttributeMaxDynamicSharedMemorySize, smemA);
    cudaFuncSetAttribute((const void*)flash_kernel<32,128>,
                         cudaFuncAttributeMaxDynamicSharedMemorySize, smemC);

    // ---------------- CSA1: N1=784 (p832), N2=196 (p256), H=64, NS=1
    proj_plain_kernel<160,64><<<dim3(ceil_div(256,32),2), 256>>>(
        f0, cas1_w2, x2abf, x2aT, 196, 256, (size_t)160*196);
    proj_x1_kernel<128,64><<<dim3(ceil_div(832,32),2), 256>>>(
        f1, cas1_w1, x1a, x1abf, 784, 832, (size_t)128*784);
    flash_kernel<64,64><<<dim3(NBA,2,1), 128, smemA>>>(
        x1abf, x2abf, x2aT, Oa, BSa, 784, 196, 832, 256);

    // ---------------- CSA2: N1=3136, N2=784 (p832), H=64, NS=4
    proj_norm_kernel<64,64,1><<<dim3(ceil_div(832,16),2), 512>>>(
        Oa, 0, x1a, BSa, NBA, cas2_w2, x2bbf, x2bT, 784, 832);
    proj_x1_kernel<64,64><<<dim3(ceil_div(3136,32),2), 256>>>(
        f2, cas2_w1, x1b, x1bbf, 3136, 3136, (size_t)64*3136);
    flash_kernel<64,64><<<dim3(NBB,2,4), 128, smemA>>>(
        x1bbf, x2bbf, x2bT, Ob, BSb, 3136, 784, 3136, 832);

    // ---------------- CSA3: N1=12544, N2=3136, H=32, NS=4
    proj_norm_kernel<64,32,4><<<dim3(ceil_div(3136,16),2), 512>>>(
        Ob, OSZ_B, x1b, BSb, 4*NBB, cas3_w2, x2cbf, x2cT, 3136, 3136);
    proj_x1_kernel<32,32><<<dim3(ceil_div(12544,32),2), 256>>>(
        f3, cas3_w1, x1c, x1cbf, 12544, 12544, (size_t)32*12544);
    flash_kernel<32,128><<<dim3(NBC,2,4), 256, smemC>>>(
        x1cbf, x2cbf, x2cT, Oc, BSc, 12544, 3136, 12544, 3136);

    // ---------------- decoder (softmax-normalization folded in)
    msr_kernel<64,64,32,true,true,true,4><<<dim3(ceil_div(3136,128),2), 128>>>(
        Ob, OSZ_B, x1b, BSb, 4*NBB, Oa, x1a, BSa, NBA,
        m1w1, m1b1, m1w2, m1b2, y1, 56, 28);
    msr_kernel<32,32,16,true,false,true,4><<<dim3(ceil_div(12544,128),2), 128>>>(
        Oc, OSZ_C, x1c, BSc, 4*NBC, y1, nullptr, nullptr, 0,
        m2w1, m2b1, m2w2, m2b2, y2, 112, 56);
    msr_kernel<16,16,8,false,false,false,1><<<dim3(ceil_div(50176,128),2), 128>>>(
        nullptr, 0, nullptr, nullptr, 0, y2, nullptr, nullptr, 0,
        m3w1, m3b1, m3w2, m3b2, y3, 224, 112);
    msr_kernel<8,2,1,false,false,false,1><<<dim3(ceil_div(200704,128),2), 128>>>(
        nullptr, 0, nullptr, nullptr, 0, y3, nullptr, nullptr, 0,
        m4w1, m4b1, m4w2, m4b2, outp, 448, 224);

    (void)in_sizes; (void)n_in; (void)out_size;
}

// round 15
// speedup vs baseline: 1.1913x; 1.1381x over previous
#include <cuda_runtime.h>
#include <cuda_bf16.h>
#include <math.h>
#include <stdint.h>

// ============================================================================
// fp32 scratch  (Ob/Oc have 4 k-split partial buffers)
// ============================================================================
static constexpr size_t OSZ_B = (size_t)2*3136*64;    // one split buffer
static constexpr size_t OSZ_C = (size_t)2*12544*32;

static constexpr size_t SZ_X1A = (size_t)2*784*64;
static constexpr size_t SZ_OA  = (size_t)2*784*64;
static constexpr size_t SZ_X1B = (size_t)2*3136*64;
static constexpr size_t SZ_OB  = 4*OSZ_B;
static constexpr size_t SZ_X1C = (size_t)2*12544*32;
static constexpr size_t SZ_OC  = 4*OSZ_C;
static constexpr size_t SZ_Y1  = (size_t)2*3136*32;
static constexpr size_t SZ_Y2  = (size_t)2*12544*16;
static constexpr size_t SZ_Y3  = (size_t)2*50176*8;
static constexpr size_t SZ_BS  = (size_t)2*512;

static constexpr size_t OFF_X1A = 0;
static constexpr size_t OFF_OA  = OFF_X1A + SZ_X1A;
static constexpr size_t OFF_X1B = OFF_OA  + SZ_OA;
static constexpr size_t OFF_OB  = OFF_X1B + SZ_X1B;
static constexpr size_t OFF_X1C = OFF_OB  + SZ_OB;
static constexpr size_t OFF_OC  = OFF_X1C + SZ_X1C;
static constexpr size_t OFF_Y1  = OFF_OC  + SZ_OC;
static constexpr size_t OFF_Y2  = OFF_Y1  + SZ_Y1;
static constexpr size_t OFF_Y3  = OFF_Y2  + SZ_Y2;
static constexpr size_t OFF_BSA = OFF_Y3  + SZ_Y3;
static constexpr size_t OFF_BSB = OFF_BSA + SZ_BS;
static constexpr size_t OFF_BSC = OFF_BSB + SZ_BS;
static constexpr size_t SCRATCH_TOTAL = OFF_BSC + SZ_BS;
__device__ __align__(16) float g_scratch[SCRATCH_TOTAL];

// ============================================================================
// bf16 scratch: x1bf + x2 row-major + x2 transposed per stage (pads zeroed)
// ============================================================================
static constexpr size_t BOFF_X1A = 0;                                   // 2*832*64
static constexpr size_t BOFF_X2A = BOFF_X1A + (size_t)2*832*64;         // 2*256*64
static constexpr size_t BOFF_TA  = BOFF_X2A + (size_t)2*256*64;         // 2*64*256
static constexpr size_t BOFF_X1B = BOFF_TA  + (size_t)2*64*256;         // 2*3136*64
static constexpr size_t BOFF_X2B = BOFF_X1B + (size_t)2*3136*64;        // 2*832*64
static constexpr size_t BOFF_TB  = BOFF_X2B + (size_t)2*832*64;         // 2*64*832
static constexpr size_t BOFF_X1C = BOFF_TB  + (size_t)2*64*832;         // 2*12544*32
static constexpr size_t BOFF_X2C = BOFF_X1C + (size_t)2*12544*32;       // 2*3136*32
static constexpr size_t BOFF_TC  = BOFF_X2C + (size_t)2*3136*32;        // 2*32*3136
static constexpr size_t BSCRATCH_TOTAL = BOFF_TC + (size_t)2*32*3136;
__device__ __align__(16) __nv_bfloat16 g_bf[BSCRATCH_TOTAL];

// ============================================================================
// Side stream + events for graph-captured overlap (created once, statically;
// host-side resources only — no device memory allocations).
// ============================================================================
struct StreamAux {
    cudaStream_t s1;
    cudaEvent_t ev0, evB, evC, evFB, evM1;
    StreamAux() {
        cudaStreamCreateWithFlags(&s1, cudaStreamNonBlocking);
        cudaEventCreateWithFlags(&ev0,  cudaEventDisableTiming);
        cudaEventCreateWithFlags(&evB,  cudaEventDisableTiming);
        cudaEventCreateWithFlags(&evC,  cudaEventDisableTiming);
        cudaEventCreateWithFlags(&evFB, cudaEventDisableTiming);
        cudaEventCreateWithFlags(&evM1, cudaEventDisableTiming);
    }
};
static StreamAux g_aux;

#define MMA_BF16(d, a, b)                                                      \
    asm volatile(                                                              \
        "mma.sync.aligned.m16n8k16.row.col.f32.bf16.bf16.f32 "                 \
        "{%0,%1,%2,%3},{%4,%5,%6,%7},{%8,%9},{%0,%1,%2,%3};"                   \
        : "+f"((d)[0]), "+f"((d)[1]), "+f"((d)[2]), "+f"((d)[3])               \
        : "r"((a)[0]), "r"((a)[1]), "r"((a)[2]), "r"((a)[3]),                  \
          "r"((b)[0]), "r"((b)[1]))

__device__ __forceinline__ void cp16(uint32_t saddr, const void* gptr) {
    asm volatile("cp.async.ca.shared.global [%0], [%1], 16;" :: "r"(saddr), "l"(gptr));
}
__device__ __forceinline__ uint32_t pack_bf2(float lo, float hi) {
    __nv_bfloat162 v = __floats2bfloat162_rn(lo, hi);
    return *reinterpret_cast<uint32_t*>(&v);
}

// Warp-0 deterministic partial-sum (identical everywhere -> identical Z).
__device__ __forceinline__ float warp_sum_partials(const float* bs, int NB, int lane) {
    float z = 0.f;
    for (int i = lane; i < NB; i += 32) z += bs[i];
#pragma unroll
    for (int off = 16; off > 0; off >>= 1)
        z += __shfl_xor_sync(0xffffffffu, z, off);
    return z;
}

// ============================================================================
// Plain projection (NCHW source, coalesced): X2 for CSA1 (bf16 + transpose).
// ============================================================================
template<int C, int H>
__global__ void __launch_bounds__(256) proj_plain_kernel(
    const float* __restrict__ X, const float* __restrict__ W,
    __nv_bfloat16* __restrict__ outbf, __nv_bfloat16* __restrict__ outT,
    int N, int Np, size_t bstride)
{
    __shared__ float sw[C*H];
    const int tid = threadIdx.x;
    for (int i = tid; i < C*H; i += 256) sw[i] = W[i];
    __syncthreads();
    const int b = blockIdx.y;
    const int n = blockIdx.x * 32 + (tid & 31);
    const int ty = tid >> 5;
    constexpr int HP = H / 8;
    if (n >= Np) return;

    float acc[HP];
#pragma unroll
    for (int k = 0; k < HP; k++) acc[k] = 0.f;
    if (n < N) {
        const float* xb = X + (size_t)b * bstride;
        for (int c = 0; c < C; c++) {
            float v = xb[(size_t)c * N + n];
            const float* wr = &sw[c*H + ty*HP];
#pragma unroll
            for (int k = 0; k < HP; k++) acc[k] += v * wr[k];
        }
    }
    __nv_bfloat16* obf = outbf + ((size_t)b * Np + n) * H + ty * HP;
#pragma unroll
    for (int k = 0; k < HP; k += 2)
        *reinterpret_cast<uint32_t*>(obf + k) = pack_bf2(acc[k], acc[k+1]);
    __nv_bfloat16* ot = outT + (size_t)b * H * Np;
#pragma unroll
    for (int k = 0; k < HP; k++) ot[(size_t)(ty * HP + k) * Np + n] = __float2bfloat16(acc[k]);
}

// ============================================================================
// X1 projection (NCHW source, coalesced): bf16 [Np][H] + fp32 residual [N][H].
// ============================================================================
template<int C, int H>
__global__ void __launch_bounds__(256) proj_x1_kernel(
    const float* __restrict__ X, const float* __restrict__ W,
    float* __restrict__ out32, __nv_bfloat16* __restrict__ outbf,
    int N, int Np, size_t bstride)
{
    __shared__ float sw[C*H];
    const int tid = threadIdx.x;
    for (int i = tid; i < C*H; i += 256) sw[i] = W[i];
    __syncthreads();
    const int b = blockIdx.y;
    const int n = blockIdx.x * 32 + (tid & 31);
    const int ty = tid >> 5;
    constexpr int HP = H / 8;
    if (n >= Np) return;

    float acc[HP];
#pragma unroll
    for (int k = 0; k < HP; k++) acc[k] = 0.f;
    if (n < N) {
        const float* xb = X + (size_t)b * bstride;
        for (int c = 0; c < C; c++) {
            float v = xb[(size_t)c * N + n];
            const float* wr = &sw[c*H + ty*HP];
#pragma unroll
            for (int k = 0; k < HP; k++) acc[k] += v * wr[k];
        }
    }
    __nv_bfloat16* obf = outbf + ((size_t)b * Np + n) * H + ty * HP;
#pragma unroll
    for (int k = 0; k < HP; k += 2)
        *reinterpret_cast<uint32_t*>(obf + k) = pack_bf2(acc[k], acc[k+1]);
    if (n < N) {
        float* o32 = out32 + ((size_t)b * N + n) * H + ty * HP;
#pragma unroll
        for (int k = 0; k < HP; k += 4)
            *reinterpret_cast<float4*>(o32 + k) = make_float4(acc[k], acc[k+1], acc[k+2], acc[k+3]);
    }
}

// ============================================================================
// Norm-folded projection: In(n,c) = (sum_s O_s)(n,c)/Z + xres(n,c), out = In.W
// PXB px x 16 hg x 2 C-halves per block (PXB*32 threads).
// ============================================================================
template<int C, int H, int NSPLIT, int PXB>
__global__ void __launch_bounds__(PXB*32) proj_norm_kernel(
    const float* __restrict__ O, size_t osz,
    const float* __restrict__ xres,
    const float* __restrict__ BS, int NB,
    const float* __restrict__ W,
    __nv_bfloat16* __restrict__ outbf, __nv_bfloat16* __restrict__ outT,
    int N, int Np)
{
    constexpr int THREADS = PXB * 32;
    constexpr int PPX = PXB + 1;
    constexpr int HP  = H / 16;
    __shared__ float sraw[C * PPX];
    __shared__ float sw[C * H];
    __shared__ float sacc[PXB * 16 * HP];
    __shared__ float sZ;
    const int tid = threadIdx.x;
    const int b = blockIdx.y;
    const int px0 = blockIdx.x * PXB;
    for (int i = tid; i < C*H; i += THREADS) sw[i] = W[i];
    if (tid < 32) {
        float z = warp_sum_partials(BS + (size_t)b * NB, NB, tid);
        if (tid == 0) sZ = 1.f / z;
    }
    __syncthreads();

    const float f = sZ;
    constexpr int C4 = C / 4;
    for (int i = tid; i < PXB * C4; i += THREADS) {
        int c4 = i % C4, px = i / C4;
        int n = px0 + px;
        float4 o4 = make_float4(0.f,0.f,0.f,0.f), r4 = o4;
        if (n < N) {
            size_t idx = ((size_t)b * N + n) * C + c4 * 4;
            o4 = *reinterpret_cast<const float4*>(O + idx);
#pragma unroll
            for (int s = 1; s < NSPLIT; s++) {
                float4 t = *reinterpret_cast<const float4*>(O + s * osz + idx);
                o4.x += t.x; o4.y += t.y; o4.z += t.z; o4.w += t.w;
            }
            r4 = *reinterpret_cast<const float4*>(xres + idx);
        }
        sraw[(c4*4+0) * PPX + px] = o4.x * f + r4.x;
        sraw[(c4*4+1) * PPX + px] = o4.y * f + r4.y;
        sraw[(c4*4+2) * PPX + px] = o4.z * f + r4.z;
        sraw[(c4*4+3) * PPX + px] = o4.w * f + r4.w;
    }
    __syncthreads();

    const int ch = tid / (PXB * 16);
    const int px = tid % PXB;
    const int hg = (tid / PXB) % 16;
    float acc[HP];
#pragma unroll
    for (int k = 0; k < HP; k++) acc[k] = 0.f;
#pragma unroll 4
    for (int c = ch * (C/2); c < (ch + 1) * (C/2); c++) {
        float v = sraw[c * PPX + px];
        if (HP == 4) {
            float4 w4 = *reinterpret_cast<const float4*>(&sw[c*H + hg*4]);
            acc[0] += v * w4.x; acc[1] += v * w4.y;
            acc[2] += v * w4.z; acc[3] += v * w4.w;
        } else {
            float2 w2 = *reinterpret_cast<const float2*>(&sw[c*H + hg*2]);
            acc[0] += v * w2.x; acc[1] += v * w2.y;
        }
    }
    if (ch == 1) {
#pragma unroll
        for (int k = 0; k < HP; k++) sacc[(hg * PXB + px) * HP + k] = acc[k];
    }
    __syncthreads();
    if (ch != 0) return;
    const int n = px0 + px;
    if (n >= Np) return;
#pragma unroll
    for (int k = 0; k < HP; k++) acc[k] += sacc[(hg * PXB + px) * HP + k];

    __nv_bfloat16* obf = outbf + ((size_t)b * Np + n) * H + hg * HP;
#pragma unroll
    for (int k = 0; k < HP; k += 2)
        *reinterpret_cast<uint32_t*>(obf + k) = pack_bf2(acc[k], acc[k+1]);
    __nv_bfloat16* ot = outT + (size_t)b * H * Np;
#pragma unroll
    for (int k = 0; k < HP; k++) ot[(size_t)(hg * HP + k) * Np + n] = __float2bfloat16(acc[k]);
}

// ============================================================================
// FA2-style bf16 flash CSA, X1 from precomputed bf16, no max stabilization,
// N2 k-split across blocks (blockIdx.z).
// ============================================================================
template<int H, int RB>
__global__ void __launch_bounds__(RB*2) flash_kernel(
    const __nv_bfloat16* __restrict__ X1bf,   // [b][N1p][H]
    const __nv_bfloat16* __restrict__ X2bf,   // [b][N2p][H]
    const __nv_bfloat16* __restrict__ X2T,    // [b][H][N2p]
    float* __restrict__ Oout, float* __restrict__ blocksum,
    int N1, int N2, int N1p, int N2p)
{
    constexpr int THREADS = RB * 2;
    constexpr int MB = 64;
    constexpr int PH = H + 8;
    constexpr int PM = MB + 8;
    constexpr int KSQ = H / 16;
    constexpr int NTS = MB / 8;
    constexpr int KSA = MB / 16;
    constexpr int NTO = H / 8;
    constexpr int CPR = H * 2 / 16;

    extern __shared__ __nv_bfloat16 smh[];
    __nv_bfloat16* sX1 = smh;                    // RB*PH
    __nv_bfloat16* sX2 = sX1 + RB*PH;            // 2*MB*PH
    __nv_bfloat16* sT  = sX2 + 2*MB*PH;          // 2*H*PM

    const int b = blockIdx.y;
    const int split = blockIdx.z;
    const int NS = gridDim.z;
    const int row0 = blockIdx.x * RB;
    const int tid = threadIdx.x, w = tid >> 5, lane = tid & 31;
    const int g = lane >> 2, t4 = lane & 3;
    const int wrow = w * 16;

    float* Op = Oout + (size_t)split * 2 * N1 * H;

    // ---- load X1 tile (bf16, padded rows already zeroed by proj)
    const __nv_bfloat16* x1 = X1bf + (size_t)b * N1p * H;
    for (int c = tid; c < RB * CPR; c += THREADS) {
        int r = c / CPR, k = c % CPR;
        uint4 v = *reinterpret_cast<const uint4*>(x1 + (size_t)(row0 + r) * H + k * 8);
        *reinterpret_cast<uint4*>(sX1 + r * PH + k * 8) = v;
    }

    const __nv_bfloat16* x2 = X2bf + (size_t)b * N2p * H;
    const __nv_bfloat16* xt = X2T  + (size_t)b * H * N2p;
    const int T = (N2 + MB - 1) / MB;
    const int t0 = (T * split) / NS;
    const int t1 = (T * (split + 1)) / NS;

    auto prefetch = [&](int t) {
        int buf = t & 1;
        uint32_t d2 = (uint32_t)__cvta_generic_to_shared(sX2 + buf * MB * PH);
        const __nv_bfloat16* src = x2 + (size_t)t * MB * H;
        for (int c = tid; c < MB * CPR; c += THREADS) {
            int r = c / CPR, k = c % CPR;
            cp16(d2 + (r * PH + k * 8) * 2, src + (size_t)r * H + k * 8);
        }
        uint32_t dT = (uint32_t)__cvta_generic_to_shared(sT + buf * H * PM);
        for (int c = tid; c < H * 8; c += THREADS) {
            int r = c / 8, k = c % 8;
            cp16(dT + (r * PM + k * 8) * 2, xt + (size_t)r * N2p + (size_t)t * MB + k * 8);
        }
        asm volatile("cp.async.commit_group;");
    };

    prefetch(t0);

    float s0 = 0.f, s1 = 0.f;
    float o[NTO][4];
#pragma unroll
    for (int nt = 0; nt < NTO; nt++)
#pragma unroll
        for (int k = 0; k < 4; k++) o[nt][k] = 0.f;

    for (int t = t0; t < t1; t++) {
        asm volatile("cp.async.wait_group 0;");
        __syncthreads();
        if (t + 1 < t1) prefetch(t + 1);
        const __nv_bfloat16* bX2 = sX2 + (t & 1) * MB * PH;
        const __nv_bfloat16* bT  = sT  + (t & 1) * H * PM;

        float sacc[NTS][4];
#pragma unroll
        for (int nt = 0; nt < NTS; nt++)
#pragma unroll
            for (int k = 0; k < 4; k++) sacc[nt][k] = 0.f;
#pragma unroll
        for (int ks = 0; ks < KSQ; ks++) {
            const int cb = ks * 16 + 2 * t4;
            uint32_t a[4];
            a[0] = *reinterpret_cast<const uint32_t*>(sX1 + (wrow + g) * PH + cb);
            a[1] = *reinterpret_cast<const uint32_t*>(sX1 + (wrow + g + 8) * PH + cb);
            a[2] = *reinterpret_cast<const uint32_t*>(sX1 + (wrow + g) * PH + cb + 8);
            a[3] = *reinterpret_cast<const uint32_t*>(sX1 + (wrow + g + 8) * PH + cb + 8);
#pragma unroll
            for (int nt = 0; nt < NTS; nt++) {
                uint32_t bb[2];
                bb[0] = *reinterpret_cast<const uint32_t*>(bX2 + (nt * 8 + g) * PH + cb);
                bb[1] = *reinterpret_cast<const uint32_t*>(bX2 + (nt * 8 + g) * PH + cb + 8);
                MMA_BF16(sacc[nt], a, bb);
            }
        }

        const int limit = N2 - t * MB;
        const bool full = (limit >= MB);

        // ---- P = exp(S) directly (scores bounded, no max needed)
        uint32_t pA[KSA][4];
#pragma unroll
        for (int nt = 0; nt < NTS; nt++) {
            int c0 = nt * 8 + 2 * t4;
            float p0 = (full || c0     < limit) ? __expf(sacc[nt][0]) : 0.f;
            float p1 = (full || c0 + 1 < limit) ? __expf(sacc[nt][1]) : 0.f;
            float p2 = (full || c0     < limit) ? __expf(sacc[nt][2]) : 0.f;
            float p3 = (full || c0 + 1 < limit) ? __expf(sacc[nt][3]) : 0.f;
            s0 += p0 + p1; s1 += p2 + p3;
            pA[nt >> 1][(nt & 1) * 2 + 0] = pack_bf2(p0, p1);
            pA[nt >> 1][(nt & 1) * 2 + 1] = pack_bf2(p2, p3);
        }

        // ---- O += P . X2
#pragma unroll
        for (int ks = 0; ks < KSA; ks++) {
#pragma unroll
            for (int nt = 0; nt < NTO; nt++) {
                const int rb2 = (nt * 8 + g) * PM + ks * 16 + 2 * t4;
                uint32_t bb[2];
                bb[0] = *reinterpret_cast<const uint32_t*>(bT + rb2);
                bb[1] = *reinterpret_cast<const uint32_t*>(bT + rb2 + 8);
                MMA_BF16(o[nt], pA[ks], bb);
            }
        }
    }

    // ---- final row-sum reduce over t4 quad
    s0 += __shfl_xor_sync(0xffffffffu, s0, 1);
    s0 += __shfl_xor_sync(0xffffffffu, s0, 2);
    s1 += __shfl_xor_sync(0xffffffffu, s1, 1);
    s1 += __shfl_xor_sync(0xffffffffu, s1, 2);

    const int gr0 = row0 + wrow + g;
    const int gr1 = gr0 + 8;
    {
        if (gr0 < N1) {
            float* dst = Op + ((size_t)b * N1 + gr0) * H;
#pragma unroll
            for (int nt = 0; nt < NTO; nt++)
                *reinterpret_cast<float2*>(dst + nt * 8 + 2 * t4) = make_float2(o[nt][0], o[nt][1]);
        }
        if (gr1 < N1) {
            float* dst = Op + ((size_t)b * N1 + gr1) * H;
#pragma unroll
            for (int nt = 0; nt < NTO; nt++)
                *reinterpret_cast<float2*>(dst + nt * 8 + 2 * t4) = make_float2(o[nt][2], o[nt][3]);
        }
    }

    // ---- per-block deterministic Z partial (padded rows masked to 0)
    __syncthreads();
    float* sRS = (float*)smh;
    if (t4 == 0) {
        sRS[wrow + g]     = (gr0 < N1) ? s0 : 0.f;
        sRS[wrow + g + 8] = (gr1 < N1) ? s1 : 0.f;
    }
    __syncthreads();
    if (tid == 0) {
        float z = 0.f;
        for (int r = 0; r < RB; r++) z += sRS[r];
        blocksum[((size_t)b * NS + split) * gridDim.x + blockIdx.x] = z;
    }
}

// ============================================================================
// MSR with optional folded softmax-normalization (Z from block partials).
// BNS: number of base O k-split partials to sum.
// ============================================================================
__device__ __forceinline__ float4 f4fma(float4 a, float s, float4 acc) {
    acc.x += a.x * s; acc.y += a.y * s; acc.z += a.z * s; acc.w += a.w * s;
    return acc;
}

template<int CIN, int CHID, int COUT, bool HASBASE, bool PREVNORM, bool BASENORM, int BNS>
__global__ void __launch_bounds__(128) msr_kernel(
    const float* __restrict__ baseO, size_t bosz,
    const float* __restrict__ basex1,
    const float* __restrict__ baseBS, int baseNB,
    const float* __restrict__ prevO, const float* __restrict__ prevx1,
    const float* __restrict__ prevBS, int prevNB,
    const float* __restrict__ w1, const float* __restrict__ b1,
    const float* __restrict__ w2, const float* __restrict__ b2,
    float* __restrict__ out, int Hout, int Hin)
{
    __shared__ float sw1[CIN * CHID];
    __shared__ float sw2[CHID * COUT];
    __shared__ float sb1[CHID];
    __shared__ float sb2[COUT];
    __shared__ float sZp, sZb;
    const int tid = threadIdx.x;
    const int b = blockIdx.y;
    for (int i = tid; i < CIN * CHID; i += 128) sw1[i] = w1[i];
    for (int i = tid; i < CHID * COUT; i += 128) sw2[i] = w2[i];
    if (tid < CHID) sb1[tid] = b1[tid];
    if (tid < COUT) sb2[tid] = b2[tid];
    if (PREVNORM && tid >= 32 && tid < 64) {
        float z = warp_sum_partials(prevBS + (size_t)b * prevNB, prevNB, tid - 32);
        if (tid == 32) sZp = 1.f / z;
    }
    if (BASENORM && tid < 32) {
        float z = warp_sum_partials(baseBS + (size_t)b * baseNB, baseNB, tid);
        if (tid == 0) sZb = 1.f / z;
    }
    __syncthreads();

    const int N = Hout * Hout;
    const int n = blockIdx.x * 128 + tid;
    if (n >= N) return;
    const int oy = n / Hout, ox = n % Hout;

    int y0 = (oy - 1) >> 1; int y1v = y0 + 1;
    const float wy1 = (oy & 1) ? 0.25f : 0.75f; const float wy0 = 1.f - wy1;
    y0 = max(y0, 0); y1v = min(y1v, Hin - 1);
    int x0 = (ox - 1) >> 1; int x1v = x0 + 1;
    const float wx1 = (ox & 1) ? 0.25f : 0.75f; const float wx0 = 1.f - wx1;
    x0 = max(x0, 0); x1v = min(x1v, Hin - 1);

    const int Nin = Hin * Hin;
    const int p00 = y0 * Hin + x0,  p01 = y0 * Hin + x1v;
    const int p10 = y1v * Hin + x0, p11 = y1v * Hin + x1v;
    const float w00 = wy0 * wx0, w01 = wy0 * wx1, w10 = wy1 * wx0, w11 = wy1 * wx1;

    const float* q00 = prevO + ((size_t)b * Nin + p00) * CIN;
    const float* q01 = prevO + ((size_t)b * Nin + p01) * CIN;
    const float* q10 = prevO + ((size_t)b * Nin + p10) * CIN;
    const float* q11 = prevO + ((size_t)b * Nin + p11) * CIN;

    float fp = 0.f;
    const float* r00 = nullptr; const float* r01 = nullptr;
    const float* r10 = nullptr; const float* r11 = nullptr;
    if (PREVNORM) {
        fp = sZp;
        r00 = prevx1 + ((size_t)b * Nin + p00) * CIN;
        r01 = prevx1 + ((size_t)b * Nin + p01) * CIN;
        r10 = prevx1 + ((size_t)b * Nin + p10) * CIN;
        r11 = prevx1 + ((size_t)b * Nin + p11) * CIN;
    }
    const float* bO = nullptr; const float* bR = nullptr; float fb = 0.f;
    if (HASBASE) {
        bO = baseO + ((size_t)b * N + n) * CIN;
        if (BASENORM) {
            fb = sZb;
            bR = basex1 + ((size_t)b * N + n) * CIN;
        }
    }

    float hid[CHID];
#pragma unroll
    for (int j = 0; j < CHID; j++) hid[j] = sb1[j];

#pragma unroll
    for (int c = 0; c < CIN; c += 4) {
        float4 a00 = *reinterpret_cast<const float4*>(q00 + c);
        float4 a01 = *reinterpret_cast<const float4*>(q01 + c);
        float4 a10 = *reinterpret_cast<const float4*>(q10 + c);
        float4 a11 = *reinterpret_cast<const float4*>(q11 + c);
        if (PREVNORM) {
            float4 t;
            t = *reinterpret_cast<const float4*>(r00 + c);
            a00 = make_float4(a00.x*fp+t.x, a00.y*fp+t.y, a00.z*fp+t.z, a00.w*fp+t.w);
            t = *reinterpret_cast<const float4*>(r01 + c);
            a01 = make_float4(a01.x*fp+t.x, a01.y*fp+t.y, a01.z*fp+t.z, a01.w*fp+t.w);
            t = *reinterpret_cast<const float4*>(r10 + c);
            a10 = make_float4(a10.x*fp+t.x, a10.y*fp+t.y, a10.z*fp+t.z, a10.w*fp+t.w);
            t = *reinterpret_cast<const float4*>(r11 + c);
            a11 = make_float4(a11.x*fp+t.x, a11.y*fp+t.y, a11.z*fp+t.z, a11.w*fp+t.w);
        }
        float4 v = make_float4(0.f, 0.f, 0.f, 0.f);
        v = f4fma(a00, w00, v); v = f4fma(a01, w01, v);
        v = f4fma(a10, w10, v); v = f4fma(a11, w11, v);
        if (HASBASE) {
            float4 bb = *reinterpret_cast<const float4*>(bO + c);
#pragma unroll
            for (int s = 1; s < BNS; s++) {
                float4 b2 = *reinterpret_cast<const float4*>(bO + s * bosz + c);
                bb.x += b2.x; bb.y += b2.y; bb.z += b2.z; bb.w += b2.w;
            }
            if (BASENORM) {
                float4 t = *reinterpret_cast<const float4*>(bR + c);
                bb = make_float4(bb.x*fb+t.x, bb.y*fb+t.y, bb.z*fb+t.z, bb.w*fb+t.w);
            }
            v.x += bb.x; v.y += bb.y; v.z += bb.z; v.w += bb.w;
        }
        const float* wr = &sw1[c * CHID];
#pragma unroll
        for (int j = 0; j < CHID; j++)
            hid[j] += v.x * wr[j] + v.y * wr[CHID + j] + v.z * wr[2*CHID + j] + v.w * wr[3*CHID + j];
    }
#pragma unroll
    for (int j = 0; j < CHID; j++) hid[j] = fminf(fmaxf(hid[j], 0.f), 6.f);

    float accv[COUT];
#pragma unroll
    for (int k = 0; k < COUT; k++) accv[k] = sb2[k];
#pragma unroll
    for (int j = 0; j < CHID; j++) {
        const float hv = hid[j];
        const float* wr = &sw2[j * COUT];
#pragma unroll
        for (int k = 0; k < COUT; k++) accv[k] += hv * wr[k];
    }
    float* ob = out + ((size_t)b * N + n) * COUT;
#pragma unroll
    for (int k = 0; k < COUT; k++) ob[k] = accv[k];
}

// ============================================================================
// Launch
// ============================================================================
static inline int ceil_div(int a, int b) { return (a + b - 1) / b; }

template<int H, int RB>
static inline int flash_smem_bytes() {
    constexpr int MB = 64, PH = H + 8, PM = MB + 8;
    return (RB*PH + 2*MB*PH + 2*H*PM) * 2;
}

extern "C" void kernel_launch(void* const* d_in, const int* in_sizes, int n_in,
                              void* d_out, int out_size)
{
    const float* f0 = (const float*)d_in[0];   // [2,160,14,14]
    const float* f1 = (const float*)d_in[1];   // [2,128,28,28]
    const float* f2 = (const float*)d_in[2];   // [2,64,56,56]
    const float* f3 = (const float*)d_in[3];   // [2,32,112,112]
    const float* cas1_w1 = (const float*)d_in[4];
    const float* cas1_w2 = (const float*)d_in[5];
    const float* cas2_w1 = (const float*)d_in[6];
    const float* cas2_w2 = (const float*)d_in[7];
    const float* cas3_w1 = (const float*)d_in[8];
    const float* cas3_w2 = (const float*)d_in[9];
    const float* m1w1 = (const float*)d_in[10]; const float* m1b1 = (const float*)d_in[11];
    const float* m1w2 = (const float*)d_in[12]; const float* m1b2 = (const float*)d_in[13];
    const float* m2w1 = (const float*)d_in[14]; const float* m2b1 = (const float*)d_in[15];
    const float* m2w2 = (const float*)d_in[16]; const float* m2b2 = (const float*)d_in[17];
    const float* m3w1 = (const float*)d_in[18]; const float* m3b1 = (const float*)d_in[19];
    const float* m3w2 = (const float*)d_in[20]; const float* m3b2 = (const float*)d_in[21];
    const float* m4w1 = (const float*)d_in[22]; const float* m4b1 = (const float*)d_in[23];
    const float* m4w2 = (const float*)d_in[24]; const float* m4b2 = (const float*)d_in[25];
    float* outp = (float*)d_out;

    float* S = nullptr;
    cudaGetSymbolAddress((void**)&S, g_scratch);
    __nv_bfloat16* B = nullptr;
    cudaGetSymbolAddress((void**)&B, g_bf);

    float* x1a = S + OFF_X1A; float* Oa = S + OFF_OA;
    float* x1b = S + OFF_X1B; float* Ob = S + OFF_OB;
    float* x1c = S + OFF_X1C; float* Oc = S + OFF_OC;
    float* y1 = S + OFF_Y1; float* y2 = S + OFF_Y2; float* y3 = S + OFF_Y3;
    float* BSa = S + OFF_BSA; float* BSb = S + OFF_BSB; float* BSc = S + OFF_BSC;

    __nv_bfloat16* x1abf = B + BOFF_X1A;
    __nv_bfloat16* x2abf = B + BOFF_X2A; __nv_bfloat16* x2aT = B + BOFF_TA;
    __nv_bfloat16* x1bbf = B + BOFF_X1B;
    __nv_bfloat16* x2bbf = B + BOFF_X2B; __nv_bfloat16* x2bT = B + BOFF_TB;
    __nv_bfloat16* x1cbf = B + BOFF_X1C;
    __nv_bfloat16* x2cbf = B + BOFF_X2C; __nv_bfloat16* x2cT = B + BOFF_TC;

    const int NBA = 832/64;      // 13 blocks, NS=1
    const int NBB = 3136/64;     // 49 blocks, NS=4
    const int NBC = 12544/128;   // 98 blocks, NS=4

    const int smemA = flash_smem_bytes<64,64>();   // 46080
    const int smemC = flash_smem_bytes<32,128>();  // 29696
    cudaFuncSetAttribute((const void*)flash_kernel<64,64>,
                         cudaFuncAttributeMaxDynamicSharedMemorySize, smemA);
    cudaFuncSetAttribute((const void*)flash_kernel<32,128>,
                         cudaFuncAttributeMaxDynamicSharedMemorySize, smemC);

    cudaStream_t s1 = g_aux.s1;

    // ---- fork: side stream handles off-critical-path work
    cudaEventRecord(g_aux.ev0, 0);
    cudaStreamWaitEvent(s1, g_aux.ev0, 0);
    proj_x1_kernel<64,64><<<dim3(ceil_div(3136,32),2), 256, 0, s1>>>(
        f2, cas2_w1, x1b, x1bbf, 3136, 3136, (size_t)64*3136);
    cudaEventRecord(g_aux.evB, s1);
    proj_x1_kernel<32,32><<<dim3(ceil_div(12544,32),2), 256, 0, s1>>>(
        f3, cas3_w1, x1c, x1cbf, 12544, 12544, (size_t)32*12544);
    cudaEventRecord(g_aux.evC, s1);

    // ---- main: CSA1 (N1=784 p832, N2=196 p256, H=64, NS=1)
    proj_plain_kernel<160,64><<<dim3(ceil_div(256,32),2), 256>>>(
        f0, cas1_w2, x2abf, x2aT, 196, 256, (size_t)160*196);
    proj_x1_kernel<128,64><<<dim3(ceil_div(832,32),2), 256>>>(
        f1, cas1_w1, x1a, x1abf, 784, 832, (size_t)128*784);
    flash_kernel<64,64><<<dim3(NBA,2,1), 128, smemA>>>(
        x1abf, x2abf, x2aT, Oa, BSa, 784, 196, 832, 256);

    // ---- CSA2 (N1=3136, N2=784 p832, H=64, NS=4); PXB=8 for more blocks
    proj_norm_kernel<64,64,1,8><<<dim3(ceil_div(832,8),2), 256>>>(
        Oa, 0, x1a, BSa, NBA, cas2_w2, x2bbf, x2bT, 784, 832);
    cudaStreamWaitEvent(0, g_aux.evB, 0);
    flash_kernel<64,64><<<dim3(NBB,2,4), 128, smemA>>>(
        x1bbf, x2bbf, x2bT, Ob, BSb, 3136, 784, 3136, 832);
    cudaEventRecord(g_aux.evFB, 0);

    // ---- side: msr1 (needs flash_b + flash_a outputs) overlaps CSA3
    cudaStreamWaitEvent(s1, g_aux.evFB, 0);
    msr_kernel<64,64,32,true,true,true,4><<<dim3(ceil_div(3136,128),2), 128, 0, s1>>>(
        Ob, OSZ_B, x1b, BSb, 4*NBB, Oa, x1a, BSa, NBA,
        m1w1, m1b1, m1w2, m1b2, y1, 56, 28);
    cudaEventRecord(g_aux.evM1, s1);

    // ---- main: CSA3 (N1=12544, N2=3136, H=32, NS=4)
    proj_norm_kernel<64,32,4,16><<<dim3(ceil_div(3136,16),2), 512>>>(
        Ob, OSZ_B, x1b, BSb, 4*NBB, cas3_w2, x2cbf, x2cT, 3136, 3136);
    cudaStreamWaitEvent(0, g_aux.evC, 0);
    flash_kernel<32,128><<<dim3(NBC,2,4), 256, smemC>>>(
        x1cbf, x2cbf, x2cT, Oc, BSc, 12544, 3136, 12544, 3136);

    // ---- decoder tail (join msr1)
    cudaStreamWaitEvent(0, g_aux.evM1, 0);
    msr_kernel<32,32,16,true,false,true,4><<<dim3(ceil_div(12544,128),2), 128>>>(
        Oc, OSZ_C, x1c, BSc, 4*NBC, y1, nullptr, nullptr, 0,
        m2w1, m2b1, m2w2, m2b2, y2, 112, 56);
    msr_kernel<16,16,8,false,false,false,1><<<dim3(ceil_div(50176,128),2), 128>>>(
        nullptr, 0, nullptr, nullptr, 0, y2, nullptr, nullptr, 0,
        m3w1, m3b1, m3w2, m3b2, y3, 224, 112);
    msr_kernel<8,2,1,false,false,false,1><<<dim3(ceil_div(200704,128),2), 128>>>(
        nullptr, 0, nullptr, nullptr, 0, y3, nullptr, nullptr, 0,
        m4w1, m4b1, m4w2, m4b2, outp, 448, 224);

    (void)in_sizes; (void)n_in; (void)out_size;
}

// round 16
// speedup vs baseline: 1.2573x; 1.0554x over previous
#include <cuda_runtime.h>
#include <cuda_bf16.h>
#include <math.h>
#include <stdint.h>

// ============================================================================
// fp32 scratch  (Ob/Oc have 4 k-split partial buffers)
// ============================================================================
static constexpr size_t OSZ_B = (size_t)2*3136*64;    // one split buffer
static constexpr size_t OSZ_C = (size_t)2*12544*32;

static constexpr size_t SZ_X1A = (size_t)2*784*64;
static constexpr size_t SZ_OA  = (size_t)2*784*64;
static constexpr size_t SZ_X1B = (size_t)2*3136*64;
static constexpr size_t SZ_OB  = 4*OSZ_B;
static constexpr size_t SZ_X1C = (size_t)2*12544*32;
static constexpr size_t SZ_OC  = 4*OSZ_C;
static constexpr size_t SZ_Y1  = (size_t)2*3136*32;
static constexpr size_t SZ_Y2  = (size_t)2*12544*16;
static constexpr size_t SZ_Y3  = (size_t)2*50176*8;
static constexpr size_t SZ_BS  = (size_t)2*512;

static constexpr size_t OFF_X1A = 0;
static constexpr size_t OFF_OA  = OFF_X1A + SZ_X1A;
static constexpr size_t OFF_X1B = OFF_OA  + SZ_OA;
static constexpr size_t OFF_OB  = OFF_X1B + SZ_X1B;
static constexpr size_t OFF_X1C = OFF_OB  + SZ_OB;
static constexpr size_t OFF_OC  = OFF_X1C + SZ_X1C;
static constexpr size_t OFF_Y1  = OFF_OC  + SZ_OC;
static constexpr size_t OFF_Y2  = OFF_Y1  + SZ_Y1;
static constexpr size_t OFF_Y3  = OFF_Y2  + SZ_Y2;
static constexpr size_t OFF_BSA = OFF_Y3  + SZ_Y3;
static constexpr size_t OFF_BSB = OFF_BSA + SZ_BS;
static constexpr size_t OFF_BSC = OFF_BSB + SZ_BS;
static constexpr size_t SCRATCH_TOTAL = OFF_BSC + SZ_BS;
__device__ __align__(16) float g_scratch[SCRATCH_TOTAL];

// ============================================================================
// bf16 scratch: x1bf + x2 row-major + x2 transposed per stage (pads zeroed)
// ============================================================================
static constexpr size_t BOFF_X1A = 0;                                   // 2*832*64
static constexpr size_t BOFF_X2A = BOFF_X1A + (size_t)2*832*64;         // 2*256*64
static constexpr size_t BOFF_TA  = BOFF_X2A + (size_t)2*256*64;         // 2*64*256
static constexpr size_t BOFF_X1B = BOFF_TA  + (size_t)2*64*256;         // 2*3136*64
static constexpr size_t BOFF_X2B = BOFF_X1B + (size_t)2*3136*64;        // 2*832*64
static constexpr size_t BOFF_TB  = BOFF_X2B + (size_t)2*832*64;         // 2*64*832
static constexpr size_t BOFF_X1C = BOFF_TB  + (size_t)2*64*832;         // 2*12544*32
static constexpr size_t BOFF_X2C = BOFF_X1C + (size_t)2*12544*32;       // 2*3136*32
static constexpr size_t BOFF_TC  = BOFF_X2C + (size_t)2*3136*32;        // 2*32*3136
static constexpr size_t BSCRATCH_TOTAL = BOFF_TC + (size_t)2*32*3136;
__device__ __align__(16) __nv_bfloat16 g_bf[BSCRATCH_TOTAL];

// ============================================================================
// Side stream + events (host resources, created once, no device allocs).
// ============================================================================
struct StreamAux {
    cudaStream_t s1;
    cudaEvent_t ev0, evB, evC, evFB, evM1;
    StreamAux() {
        cudaStreamCreateWithFlags(&s1, cudaStreamNonBlocking);
        cudaEventCreateWithFlags(&ev0,  cudaEventDisableTiming);
        cudaEventCreateWithFlags(&evB,  cudaEventDisableTiming);
        cudaEventCreateWithFlags(&evC,  cudaEventDisableTiming);
        cudaEventCreateWithFlags(&evFB, cudaEventDisableTiming);
        cudaEventCreateWithFlags(&evM1, cudaEventDisableTiming);
    }
};
static StreamAux g_aux;

#define MMA_BF16(d, a, b)                                                      \
    asm volatile(                                                              \
        "mma.sync.aligned.m16n8k16.row.col.f32.bf16.bf16.f32 "                 \
        "{%0,%1,%2,%3},{%4,%5,%6,%7},{%8,%9},{%0,%1,%2,%3};"                   \
        : "+f"((d)[0]), "+f"((d)[1]), "+f"((d)[2]), "+f"((d)[3])               \
        : "r"((a)[0]), "r"((a)[1]), "r"((a)[2]), "r"((a)[3]),                  \
          "r"((b)[0]), "r"((b)[1]))

__device__ __forceinline__ void cp16(uint32_t saddr, const void* gptr) {
    asm volatile("cp.async.ca.shared.global [%0], [%1], 16;" :: "r"(saddr), "l"(gptr));
}
__device__ __forceinline__ uint32_t pack_bf2(float lo, float hi) {
    __nv_bfloat162 v = __floats2bfloat162_rn(lo, hi);
    return *reinterpret_cast<uint32_t*>(&v);
}

// Warp-0 deterministic partial-sum (identical everywhere -> identical Z).
__device__ __forceinline__ float warp_sum_partials(const float* bs, int NB, int lane) {
    float z = 0.f;
    for (int i = lane; i < NB; i += 32) z += bs[i];
#pragma unroll
    for (int off = 16; off > 0; off >>= 1)
        z += __shfl_xor_sync(0xffffffffu, z, off);
    return z;
}

// ============================================================================
// Plain projection (NCHW source, coalesced): X2 for CSA1 (bf16 + transpose).
// ============================================================================
template<int C, int H>
__global__ void __launch_bounds__(256) proj_plain_kernel(
    const float* __restrict__ X, const float* __restrict__ W,
    __nv_bfloat16* __restrict__ outbf, __nv_bfloat16* __restrict__ outT,
    int N, int Np, size_t bstride)
{
    __shared__ float sw[C*H];
    const int tid = threadIdx.x;
    for (int i = tid; i < C*H; i += 256) sw[i] = W[i];
    __syncthreads();
    const int b = blockIdx.y;
    const int n = blockIdx.x * 32 + (tid & 31);
    const int ty = tid >> 5;
    constexpr int HP = H / 8;
    if (n >= Np) return;

    float acc[HP];
#pragma unroll
    for (int k = 0; k < HP; k++) acc[k] = 0.f;
    if (n < N) {
        const float* xb = X + (size_t)b * bstride;
        for (int c = 0; c < C; c++) {
            float v = xb[(size_t)c * N + n];
            const float* wr = &sw[c*H + ty*HP];
#pragma unroll
            for (int k = 0; k < HP; k++) acc[k] += v * wr[k];
        }
    }
    __nv_bfloat16* obf = outbf + ((size_t)b * Np + n) * H + ty * HP;
#pragma unroll
    for (int k = 0; k < HP; k += 2)
        *reinterpret_cast<uint32_t*>(obf + k) = pack_bf2(acc[k], acc[k+1]);
    __nv_bfloat16* ot = outT + (size_t)b * H * Np;
#pragma unroll
    for (int k = 0; k < HP; k++) ot[(size_t)(ty * HP + k) * Np + n] = __float2bfloat16(acc[k]);
}

// ============================================================================
// X1 projection, high-parallelism geometry (mirrors proj_norm):
// stage NCHW tile to smem [c][px], 512 thr = 16px x 16hg x 2 C-halves,
// vector weight loads, smem half-combine. bf16 [Np][H] + fp32 residual [N][H].
// ============================================================================
template<int C, int H>
__global__ void __launch_bounds__(512) proj_x1_kernel(
    const float* __restrict__ X, const float* __restrict__ W,
    float* __restrict__ out32, __nv_bfloat16* __restrict__ outbf,
    int N, int Np, size_t bstride)
{
    constexpr int PXB = 16;
    constexpr int PPX = PXB + 1;
    constexpr int HP  = H / 16;            // 4 (H=64) or 2 (H=32)
    __shared__ float sraw[C * PPX];
    __shared__ float sw[C * H];
    __shared__ float sacc[PXB * 16 * HP];
    const int tid = threadIdx.x;
    const int b = blockIdx.y;
    const int px0 = blockIdx.x * PXB;
    for (int i = tid; i < C*H; i += 512) sw[i] = W[i];

    const float* xb = X + (size_t)b * bstride;
    for (int i = tid; i < C * PXB; i += 512) {
        int c = i / PXB, px = i % PXB;
        int n = px0 + px;
        sraw[c * PPX + px] = (n < N) ? xb[(size_t)c * N + n] : 0.f;
    }
    __syncthreads();

    const int ch = tid >> 8;               // 0..1 C-half
    const int px = tid & (PXB - 1);
    const int hg = (tid >> 4) & 15;        // 0..15
    float acc[HP];
#pragma unroll
    for (int k = 0; k < HP; k++) acc[k] = 0.f;
#pragma unroll 4
    for (int c = ch * (C/2); c < (ch + 1) * (C/2); c++) {
        float v = sraw[c * PPX + px];
        if (HP == 4) {
            float4 w4 = *reinterpret_cast<const float4*>(&sw[c*H + hg*4]);
            acc[0] += v * w4.x; acc[1] += v * w4.y;
            acc[2] += v * w4.z; acc[3] += v * w4.w;
        } else {
            float2 w2 = *reinterpret_cast<const float2*>(&sw[c*H + hg*2]);
            acc[0] += v * w2.x; acc[1] += v * w2.y;
        }
    }
    if (ch == 1) {
#pragma unroll
        for (int k = 0; k < HP; k++) sacc[(hg * PXB + px) * HP + k] = acc[k];
    }
    __syncthreads();
    if (ch != 0) return;
    const int n = px0 + px;
    if (n >= Np) return;
#pragma unroll
    for (int k = 0; k < HP; k++) acc[k] += sacc[(hg * PXB + px) * HP + k];

    __nv_bfloat16* obf = outbf + ((size_t)b * Np + n) * H + hg * HP;
#pragma unroll
    for (int k = 0; k < HP; k += 2)
        *reinterpret_cast<uint32_t*>(obf + k) = pack_bf2(acc[k], acc[k+1]);
    if (n < N) {
        float* o32 = out32 + ((size_t)b * N + n) * H + hg * HP;
        if (HP == 4)
            *reinterpret_cast<float4*>(o32) = make_float4(acc[0], acc[1], acc[2], acc[3]);
        else
            *reinterpret_cast<float2*>(o32) = make_float2(acc[0], acc[1]);
    }
}

// ============================================================================
// Norm-folded projection: In(n,c) = (sum_s O_s)(n,c)/Z + xres(n,c), out = In.W
// PXB px x 16 hg x 2 C-halves per block (PXB*32 threads).
// ============================================================================
template<int C, int H, int NSPLIT, int PXB>
__global__ void __launch_bounds__(PXB*32) proj_norm_kernel(
    const float* __restrict__ O, size_t osz,
    const float* __restrict__ xres,
    const float* __restrict__ BS, int NB,
    const float* __restrict__ W,
    __nv_bfloat16* __restrict__ outbf, __nv_bfloat16* __restrict__ outT,
    int N, int Np)
{
    constexpr int THREADS = PXB * 32;
    constexpr int PPX = PXB + 1;
    constexpr int HP  = H / 16;
    __shared__ float sraw[C * PPX];
    __shared__ float sw[C * H];
    __shared__ float sacc[PXB * 16 * HP];
    __shared__ float sZ;
    const int tid = threadIdx.x;
    const int b = blockIdx.y;
    const int px0 = blockIdx.x * PXB;
    for (int i = tid; i < C*H; i += THREADS) sw[i] = W[i];
    if (tid < 32) {
        float z = warp_sum_partials(BS + (size_t)b * NB, NB, tid);
        if (tid == 0) sZ = 1.f / z;
    }
    __syncthreads();

    const float f = sZ;
    constexpr int C4 = C / 4;
    for (int i = tid; i < PXB * C4; i += THREADS) {
        int c4 = i % C4, px = i / C4;
        int n = px0 + px;
        float4 o4 = make_float4(0.f,0.f,0.f,0.f), r4 = o4;
        if (n < N) {
            size_t idx = ((size_t)b * N + n) * C + c4 * 4;
            o4 = *reinterpret_cast<const float4*>(O + idx);
#pragma unroll
            for (int s = 1; s < NSPLIT; s++) {
                float4 t = *reinterpret_cast<const float4*>(O + s * osz + idx);
                o4.x += t.x; o4.y += t.y; o4.z += t.z; o4.w += t.w;
            }
            r4 = *reinterpret_cast<const float4*>(xres + idx);
        }
        sraw[(c4*4+0) * PPX + px] = o4.x * f + r4.x;
        sraw[(c4*4+1) * PPX + px] = o4.y * f + r4.y;
        sraw[(c4*4+2) * PPX + px] = o4.z * f + r4.z;
        sraw[(c4*4+3) * PPX + px] = o4.w * f + r4.w;
    }
    __syncthreads();

    const int ch = tid / (PXB * 16);
    const int px = tid % PXB;
    const int hg = (tid / PXB) % 16;
    float acc[HP];
#pragma unroll
    for (int k = 0; k < HP; k++) acc[k] = 0.f;
#pragma unroll 4
    for (int c = ch * (C/2); c < (ch + 1) * (C/2); c++) {
        float v = sraw[c * PPX + px];
        if (HP == 4) {
            float4 w4 = *reinterpret_cast<const float4*>(&sw[c*H + hg*4]);
            acc[0] += v * w4.x; acc[1] += v * w4.y;
            acc[2] += v * w4.z; acc[3] += v * w4.w;
        } else {
            float2 w2 = *reinterpret_cast<const float2*>(&sw[c*H + hg*2]);
            acc[0] += v * w2.x; acc[1] += v * w2.y;
        }
    }
    if (ch == 1) {
#pragma unroll
        for (int k = 0; k < HP; k++) sacc[(hg * PXB + px) * HP + k] = acc[k];
    }
    __syncthreads();
    if (ch != 0) return;
    const int n = px0 + px;
    if (n >= Np) return;
#pragma unroll
    for (int k = 0; k < HP; k++) acc[k] += sacc[(hg * PXB + px) * HP + k];

    __nv_bfloat16* obf = outbf + ((size_t)b * Np + n) * H + hg * HP;
#pragma unroll
    for (int k = 0; k < HP; k += 2)
        *reinterpret_cast<uint32_t*>(obf + k) = pack_bf2(acc[k], acc[k+1]);
    __nv_bfloat16* ot = outT + (size_t)b * H * Np;
#pragma unroll
    for (int k = 0; k < HP; k++) ot[(size_t)(hg * HP + k) * Np + n] = __float2bfloat16(acc[k]);
}

// ============================================================================
// FA2-style bf16 flash CSA, X1 from precomputed bf16, no max stabilization,
// N2 k-split across blocks (blockIdx.z).
// ============================================================================
template<int H, int RB>
__global__ void __launch_bounds__(RB*2) flash_kernel(
    const __nv_bfloat16* __restrict__ X1bf,   // [b][N1p][H]
    const __nv_bfloat16* __restrict__ X2bf,   // [b][N2p][H]
    const __nv_bfloat16* __restrict__ X2T,    // [b][H][N2p]
    float* __restrict__ Oout, float* __restrict__ blocksum,
    int N1, int N2, int N1p, int N2p)
{
    constexpr int THREADS = RB * 2;
    constexpr int MB = 64;
    constexpr int PH = H + 8;
    constexpr int PM = MB + 8;
    constexpr int KSQ = H / 16;
    constexpr int NTS = MB / 8;
    constexpr int KSA = MB / 16;
    constexpr int NTO = H / 8;
    constexpr int CPR = H * 2 / 16;

    extern __shared__ __nv_bfloat16 smh[];
    __nv_bfloat16* sX1 = smh;                    // RB*PH
    __nv_bfloat16* sX2 = sX1 + RB*PH;            // 2*MB*PH
    __nv_bfloat16* sT  = sX2 + 2*MB*PH;          // 2*H*PM

    const int b = blockIdx.y;
    const int split = blockIdx.z;
    const int NS = gridDim.z;
    const int row0 = blockIdx.x * RB;
    const int tid = threadIdx.x, w = tid >> 5, lane = tid & 31;
    const int g = lane >> 2, t4 = lane & 3;
    const int wrow = w * 16;

    float* Op = Oout + (size_t)split * 2 * N1 * H;

    // ---- load X1 tile (bf16, padded rows already zeroed by proj)
    const __nv_bfloat16* x1 = X1bf + (size_t)b * N1p * H;
    for (int c = tid; c < RB * CPR; c += THREADS) {
        int r = c / CPR, k = c % CPR;
        uint4 v = *reinterpret_cast<const uint4*>(x1 + (size_t)(row0 + r) * H + k * 8);
        *reinterpret_cast<uint4*>(sX1 + r * PH + k * 8) = v;
    }

    const __nv_bfloat16* x2 = X2bf + (size_t)b * N2p * H;
    const __nv_bfloat16* xt = X2T  + (size_t)b * H * N2p;
    const int T = (N2 + MB - 1) / MB;
    const int t0 = (T * split) / NS;
    const int t1 = (T * (split + 1)) / NS;

    auto prefetch = [&](int t) {
        int buf = t & 1;
        uint32_t d2 = (uint32_t)__cvta_generic_to_shared(sX2 + buf * MB * PH);
        const __nv_bfloat16* src = x2 + (size_t)t * MB * H;
        for (int c = tid; c < MB * CPR; c += THREADS) {
            int r = c / CPR, k = c % CPR;
            cp16(d2 + (r * PH + k * 8) * 2, src + (size_t)r * H + k * 8);
        }
        uint32_t dT = (uint32_t)__cvta_generic_to_shared(sT + buf * H * PM);
        for (int c = tid; c < H * 8; c += THREADS) {
            int r = c / 8, k = c % 8;
            cp16(dT + (r * PM + k * 8) * 2, xt + (size_t)r * N2p + (size_t)t * MB + k * 8);
        }
        asm volatile("cp.async.commit_group;");
    };

    prefetch(t0);

    float s0 = 0.f, s1 = 0.f;
    float o[NTO][4];
#pragma unroll
    for (int nt = 0; nt < NTO; nt++)
#pragma unroll
        for (int k = 0; k < 4; k++) o[nt][k] = 0.f;

    for (int t = t0; t < t1; t++) {
        asm volatile("cp.async.wait_group 0;");
        __syncthreads();
        if (t + 1 < t1) prefetch(t + 1);
        const __nv_bfloat16* bX2 = sX2 + (t & 1) * MB * PH;
        const __nv_bfloat16* bT  = sT  + (t & 1) * H * PM;

        float sacc[NTS][4];
#pragma unroll
        for (int nt = 0; nt < NTS; nt++)
#pragma unroll
            for (int k = 0; k < 4; k++) sacc[nt][k] = 0.f;
#pragma unroll
        for (int ks = 0; ks < KSQ; ks++) {
            const int cb = ks * 16 + 2 * t4;
            uint32_t a[4];
            a[0] = *reinterpret_cast<const uint32_t*>(sX1 + (wrow + g) * PH + cb);
            a[1] = *reinterpret_cast<const uint32_t*>(sX1 + (wrow + g + 8) * PH + cb);
            a[2] = *reinterpret_cast<const uint32_t*>(sX1 + (wrow + g) * PH + cb + 8);
            a[3] = *reinterpret_cast<const uint32_t*>(sX1 + (wrow + g + 8) * PH + cb + 8);
#pragma unroll
            for (int nt = 0; nt < NTS; nt++) {
                uint32_t bb[2];
                bb[0] = *reinterpret_cast<const uint32_t*>(bX2 + (nt * 8 + g) * PH + cb);
                bb[1] = *reinterpret_cast<const uint32_t*>(bX2 + (nt * 8 + g) * PH + cb + 8);
                MMA_BF16(sacc[nt], a, bb);
            }
        }

        const int limit = N2 - t * MB;
        const bool full = (limit >= MB);

        // ---- P = exp(S) directly (scores bounded, no max needed)
        uint32_t pA[KSA][4];
#pragma unroll
        for (int nt = 0; nt < NTS; nt++) {
            int c0 = nt * 8 + 2 * t4;
            float p0 = (full || c0     < limit) ? __expf(sacc[nt][0]) : 0.f;
            float p1 = (full || c0 + 1 < limit) ? __expf(sacc[nt][1]) : 0.f;
            float p2 = (full || c0     < limit) ? __expf(sacc[nt][2]) : 0.f;
            float p3 = (full || c0 + 1 < limit) ? __expf(sacc[nt][3]) : 0.f;
            s0 += p0 + p1; s1 += p2 + p3;
            pA[nt >> 1][(nt & 1) * 2 + 0] = pack_bf2(p0, p1);
            pA[nt >> 1][(nt & 1) * 2 + 1] = pack_bf2(p2, p3);
        }

        // ---- O += P . X2
#pragma unroll
        for (int ks = 0; ks < KSA; ks++) {
#pragma unroll
            for (int nt = 0; nt < NTO; nt++) {
                const int rb2 = (nt * 8 + g) * PM + ks * 16 + 2 * t4;
                uint32_t bb[2];
                bb[0] = *reinterpret_cast<const uint32_t*>(bT + rb2);
                bb[1] = *reinterpret_cast<const uint32_t*>(bT + rb2 + 8);
                MMA_BF16(o[nt], pA[ks], bb);
            }
        }
    }

    // ---- final row-sum reduce over t4 quad
    s0 += __shfl_xor_sync(0xffffffffu, s0, 1);
    s0 += __shfl_xor_sync(0xffffffffu, s0, 2);
    s1 += __shfl_xor_sync(0xffffffffu, s1, 1);
    s1 += __shfl_xor_sync(0xffffffffu, s1, 2);

    const int gr0 = row0 + wrow + g;
    const int gr1 = gr0 + 8;
    {
        if (gr0 < N1) {
            float* dst = Op + ((size_t)b * N1 + gr0) * H;
#pragma unroll
            for (int nt = 0; nt < NTO; nt++)
                *reinterpret_cast<float2*>(dst + nt * 8 + 2 * t4) = make_float2(o[nt][0], o[nt][1]);
        }
        if (gr1 < N1) {
            float* dst = Op + ((size_t)b * N1 + gr1) * H;
#pragma unroll
            for (int nt = 0; nt < NTO; nt++)
                *reinterpret_cast<float2*>(dst + nt * 8 + 2 * t4) = make_float2(o[nt][2], o[nt][3]);
        }
    }

    // ---- per-block deterministic Z partial (padded rows masked to 0)
    __syncthreads();
    float* sRS = (float*)smh;
    if (t4 == 0) {
        sRS[wrow + g]     = (gr0 < N1) ? s0 : 0.f;
        sRS[wrow + g + 8] = (gr1 < N1) ? s1 : 0.f;
    }
    __syncthreads();
    if (tid == 0) {
        float z = 0.f;
        for (int r = 0; r < RB; r++) z += sRS[r];
        blocksum[((size_t)b * NS + split) * gridDim.x + blockIdx.x] = z;
    }
}

// ============================================================================
// MSR with optional folded softmax-normalization (Z from block partials).
// BNS: number of base O k-split partials to sum.
// ============================================================================
__device__ __forceinline__ float4 f4fma(float4 a, float s, float4 acc) {
    acc.x += a.x * s; acc.y += a.y * s; acc.z += a.z * s; acc.w += a.w * s;
    return acc;
}

template<int CIN, int CHID, int COUT, bool HASBASE, bool PREVNORM, bool BASENORM, int BNS>
__global__ void __launch_bounds__(128) msr_kernel(
    const float* __restrict__ baseO, size_t bosz,
    const float* __restrict__ basex1,
    const float* __restrict__ baseBS, int baseNB,
    const float* __restrict__ prevO, const float* __restrict__ prevx1,
    const float* __restrict__ prevBS, int prevNB,
    const float* __restrict__ w1, const float* __restrict__ b1,
    const float* __restrict__ w2, const float* __restrict__ b2,
    float* __restrict__ out, int Hout, int Hin)
{
    __shared__ float sw1[CIN * CHID];
    __shared__ float sw2[CHID * COUT];
    __shared__ float sb1[CHID];
    __shared__ float sb2[COUT];
    __shared__ float sZp, sZb;
    const int tid = threadIdx.x;
    const int b = blockIdx.y;
    for (int i = tid; i < CIN * CHID; i += 128) sw1[i] = w1[i];
    for (int i = tid; i < CHID * COUT; i += 128) sw2[i] = w2[i];
    if (tid < CHID) sb1[tid] = b1[tid];
    if (tid < COUT) sb2[tid] = b2[tid];
    if (PREVNORM && tid >= 32 && tid < 64) {
        float z = warp_sum_partials(prevBS + (size_t)b * prevNB, prevNB, tid - 32);
        if (tid == 32) sZp = 1.f / z;
    }
    if (BASENORM && tid < 32) {
        float z = warp_sum_partials(baseBS + (size_t)b * baseNB, baseNB, tid);
        if (tid == 0) sZb = 1.f / z;
    }
    __syncthreads();

    const int N = Hout * Hout;
    const int n = blockIdx.x * 128 + tid;
    if (n >= N) return;
    const int oy = n / Hout, ox = n % Hout;

    int y0 = (oy - 1) >> 1; int y1v = y0 + 1;
    const float wy1 = (oy & 1) ? 0.25f : 0.75f; const float wy0 = 1.f - wy1;
    y0 = max(y0, 0); y1v = min(y1v, Hin - 1);
    int x0 = (ox - 1) >> 1; int x1v = x0 + 1;
    const float wx1 = (ox & 1) ? 0.25f : 0.75f; const float wx0 = 1.f - wx1;
    x0 = max(x0, 0); x1v = min(x1v, Hin - 1);

    const int Nin = Hin * Hin;
    const int p00 = y0 * Hin + x0,  p01 = y0 * Hin + x1v;
    const int p10 = y1v * Hin + x0, p11 = y1v * Hin + x1v;
    const float w00 = wy0 * wx0, w01 = wy0 * wx1, w10 = wy1 * wx0, w11 = wy1 * wx1;

    const float* q00 = prevO + ((size_t)b * Nin + p00) * CIN;
    const float* q01 = prevO + ((size_t)b * Nin + p01) * CIN;
    const float* q10 = prevO + ((size_t)b * Nin + p10) * CIN;
    const float* q11 = prevO + ((size_t)b * Nin + p11) * CIN;

    float fp = 0.f;
    const float* r00 = nullptr; const float* r01 = nullptr;
    const float* r10 = nullptr; const float* r11 = nullptr;
    if (PREVNORM) {
        fp = sZp;
        r00 = prevx1 + ((size_t)b * Nin + p00) * CIN;
        r01 = prevx1 + ((size_t)b * Nin + p01) * CIN;
        r10 = prevx1 + ((size_t)b * Nin + p10) * CIN;
        r11 = prevx1 + ((size_t)b * Nin + p11) * CIN;
    }
    const float* bO = nullptr; const float* bR = nullptr; float fb = 0.f;
    if (HASBASE) {
        bO = baseO + ((size_t)b * N + n) * CIN;
        if (BASENORM) {
            fb = sZb;
            bR = basex1 + ((size_t)b * N + n) * CIN;
        }
    }

    float hid[CHID];
#pragma unroll
    for (int j = 0; j < CHID; j++) hid[j] = sb1[j];

#pragma unroll
    for (int c = 0; c < CIN; c += 4) {
        float4 a00 = *reinterpret_cast<const float4*>(q00 + c);
        float4 a01 = *reinterpret_cast<const float4*>(q01 + c);
        float4 a10 = *reinterpret_cast<const float4*>(q10 + c);
        float4 a11 = *reinterpret_cast<const float4*>(q11 + c);
        if (PREVNORM) {
            float4 t;
            t = *reinterpret_cast<const float4*>(r00 + c);
            a00 = make_float4(a00.x*fp+t.x, a00.y*fp+t.y, a00.z*fp+t.z, a00.w*fp+t.w);
            t = *reinterpret_cast<const float4*>(r01 + c);
            a01 = make_float4(a01.x*fp+t.x, a01.y*fp+t.y, a01.z*fp+t.z, a01.w*fp+t.w);
            t = *reinterpret_cast<const float4*>(r10 + c);
            a10 = make_float4(a10.x*fp+t.x, a10.y*fp+t.y, a10.z*fp+t.z, a10.w*fp+t.w);
            t = *reinterpret_cast<const float4*>(r11 + c);
            a11 = make_float4(a11.x*fp+t.x, a11.y*fp+t.y, a11.z*fp+t.z, a11.w*fp+t.w);
        }
        float4 v = make_float4(0.f, 0.f, 0.f, 0.f);
        v = f4fma(a00, w00, v); v = f4fma(a01, w01, v);
        v = f4fma(a10, w10, v); v = f4fma(a11, w11, v);
        if (HASBASE) {
            float4 bb = *reinterpret_cast<const float4*>(bO + c);
#pragma unroll
            for (int s = 1; s < BNS; s++) {
                float4 b2 = *reinterpret_cast<const float4*>(bO + s * bosz + c);
                bb.x += b2.x; bb.y += b2.y; bb.z += b2.z; bb.w += b2.w;
            }
            if (BASENORM) {
                float4 t = *reinterpret_cast<const float4*>(bR + c);
                bb = make_float4(bb.x*fb+t.x, bb.y*fb+t.y, bb.z*fb+t.z, bb.w*fb+t.w);
            }
            v.x += bb.x; v.y += bb.y; v.z += bb.z; v.w += bb.w;
        }
        const float* wr = &sw1[c * CHID];
#pragma unroll
        for (int j = 0; j < CHID; j++)
            hid[j] += v.x * wr[j] + v.y * wr[CHID + j] + v.z * wr[2*CHID + j] + v.w * wr[3*CHID + j];
    }
#pragma unroll
    for (int j = 0; j < CHID; j++) hid[j] = fminf(fmaxf(hid[j], 0.f), 6.f);

    float accv[COUT];
#pragma unroll
    for (int k = 0; k < COUT; k++) accv[k] = sb2[k];
#pragma unroll
    for (int j = 0; j < CHID; j++) {
        const float hv = hid[j];
        const float* wr = &sw2[j * COUT];
#pragma unroll
        for (int k = 0; k < COUT; k++) accv[k] += hv * wr[k];
    }
    float* ob = out + ((size_t)b * N + n) * COUT;
#pragma unroll
    for (int k = 0; k < COUT; k++) ob[k] = accv[k];
}

// ============================================================================
// Launch
// ============================================================================
static inline int ceil_div(int a, int b) { return (a + b - 1) / b; }

template<int H, int RB>
static inline int flash_smem_bytes() {
    constexpr int MB = 64, PH = H + 8, PM = MB + 8;
    return (RB*PH + 2*MB*PH + 2*H*PM) * 2;
}

extern "C" void kernel_launch(void* const* d_in, const int* in_sizes, int n_in,
                              void* d_out, int out_size)
{
    const float* f0 = (const float*)d_in[0];   // [2,160,14,14]
    const float* f1 = (const float*)d_in[1];   // [2,128,28,28]
    const float* f2 = (const float*)d_in[2];   // [2,64,56,56]
    const float* f3 = (const float*)d_in[3];   // [2,32,112,112]
    const float* cas1_w1 = (const float*)d_in[4];
    const float* cas1_w2 = (const float*)d_in[5];
    const float* cas2_w1 = (const float*)d_in[6];
    const float* cas2_w2 = (const float*)d_in[7];
    const float* cas3_w1 = (const float*)d_in[8];
    const float* cas3_w2 = (const float*)d_in[9];
    const float* m1w1 = (const float*)d_in[10]; const float* m1b1 = (const float*)d_in[11];
    const float* m1w2 = (const float*)d_in[12]; const float* m1b2 = (const float*)d_in[13];
    const float* m2w1 = (const float*)d_in[14]; const float* m2b1 = (const float*)d_in[15];
    const float* m2w2 = (const float*)d_in[16]; const float* m2b2 = (const float*)d_in[17];
    const float* m3w1 = (const float*)d_in[18]; const float* m3b1 = (const float*)d_in[19];
    const float* m3w2 = (const float*)d_in[20]; const float* m3b2 = (const float*)d_in[21];
    const float* m4w1 = (const float*)d_in[22]; const float* m4b1 = (const float*)d_in[23];
    const float* m4w2 = (const float*)d_in[24]; const float* m4b2 = (const float*)d_in[25];
    float* outp = (float*)d_out;

    float* S = nullptr;
    cudaGetSymbolAddress((void**)&S, g_scratch);
    __nv_bfloat16* B = nullptr;
    cudaGetSymbolAddress((void**)&B, g_bf);

    float* x1a = S + OFF_X1A; float* Oa = S + OFF_OA;
    float* x1b = S + OFF_X1B; float* Ob = S + OFF_OB;
    float* x1c = S + OFF_X1C; float* Oc = S + OFF_OC;
    float* y1 = S + OFF_Y1; float* y2 = S + OFF_Y2; float* y3 = S + OFF_Y3;
    float* BSa = S + OFF_BSA; float* BSb = S + OFF_BSB; float* BSc = S + OFF_BSC;

    __nv_bfloat16* x1abf = B + BOFF_X1A;
    __nv_bfloat16* x2abf = B + BOFF_X2A; __nv_bfloat16* x2aT = B + BOFF_TA;
    __nv_bfloat16* x1bbf = B + BOFF_X1B;
    __nv_bfloat16* x2bbf = B + BOFF_X2B; __nv_bfloat16* x2bT = B + BOFF_TB;
    __nv_bfloat16* x1cbf = B + BOFF_X1C;
    __nv_bfloat16* x2cbf = B + BOFF_X2C; __nv_bfloat16* x2cT = B + BOFF_TC;

    const int NBA = 832/64;      // 13 blocks, NS=1
    const int NBB = 3136/64;     // 49 blocks, NS=4
    const int NBC = 12544/128;   // 98 blocks, NS=4

    const int smemA = flash_smem_bytes<64,64>();   // 46080
    const int smemC = flash_smem_bytes<32,128>();  // 29696
    cudaFuncSetAttribute((const void*)flash_kernel<64,64>,
                         cudaFuncAttributeMaxDynamicSharedMemorySize, smemA);
    cudaFuncSetAttribute((const void*)flash_kernel<32,128>,
                         cudaFuncAttributeMaxDynamicSharedMemorySize, smemC);

    cudaStream_t s1 = g_aux.s1;

    // ---- fork: side stream handles off-critical-path work
    cudaEventRecord(g_aux.ev0, 0);
    cudaStreamWaitEvent(s1, g_aux.ev0, 0);
    proj_x1_kernel<64,64><<<dim3(ceil_div(3136,16),2), 512, 0, s1>>>(
        f2, cas2_w1, x1b, x1bbf, 3136, 3136, (size_t)64*3136);
    cudaEventRecord(g_aux.evB, s1);
    proj_x1_kernel<32,32><<<dim3(ceil_div(12544,16),2), 512, 0, s1>>>(
        f3, cas3_w1, x1c, x1cbf, 12544, 12544, (size_t)32*12544);
    cudaEventRecord(g_aux.evC, s1);

    // ---- main: CSA1 (N1=784 p832, N2=196 p256, H=64, NS=1)
    proj_plain_kernel<160,64><<<dim3(ceil_div(256,32),2), 256>>>(
        f0, cas1_w2, x2abf, x2aT, 196, 256, (size_t)160*196);
    proj_x1_kernel<128,64><<<dim3(ceil_div(832,16),2), 512>>>(
        f1, cas1_w1, x1a, x1abf, 784, 832, (size_t)128*784);
    flash_kernel<64,64><<<dim3(NBA,2,1), 128, smemA>>>(
        x1abf, x2abf, x2aT, Oa, BSa, 784, 196, 832, 256);

    // ---- CSA2 (N1=3136, N2=784 p832, H=64, NS=4); PXB=8 for more blocks
    proj_norm_kernel<64,64,1,8><<<dim3(ceil_div(832,8),2), 256>>>(
        Oa, 0, x1a, BSa, NBA, cas2_w2, x2bbf, x2bT, 784, 832);
    cudaStreamWaitEvent(0, g_aux.evB, 0);
    flash_kernel<64,64><<<dim3(NBB,2,4), 128, smemA>>>(
        x1bbf, x2bbf, x2bT, Ob, BSb, 3136, 784, 3136, 832);
    cudaEventRecord(g_aux.evFB, 0);

    // ---- side: msr1 (needs flash_b + flash_a outputs) overlaps CSA3
    cudaStreamWaitEvent(s1, g_aux.evFB, 0);
    msr_kernel<64,64,32,true,true,true,4><<<dim3(ceil_div(3136,128),2), 128, 0, s1>>>(
        Ob, OSZ_B, x1b, BSb, 4*NBB, Oa, x1a, BSa, NBA,
        m1w1, m1b1, m1w2, m1b2, y1, 56, 28);
    cudaEventRecord(g_aux.evM1, s1);

    // ---- main: CSA3 (N1=12544, N2=3136, H=32, NS=4)
    proj_norm_kernel<64,32,4,16><<<dim3(ceil_div(3136,16),2), 512>>>(
        Ob, OSZ_B, x1b, BSb, 4*NBB, cas3_w2, x2cbf, x2cT, 3136, 3136);
    cudaStreamWaitEvent(0, g_aux.evC, 0);
    flash_kernel<32,128><<<dim3(NBC,2,4), 256, smemC>>>(
        x1cbf, x2cbf, x2cT, Oc, BSc, 12544, 3136, 12544, 3136);

    // ---- decoder tail (join msr1)
    cudaStreamWaitEvent(0, g_aux.evM1, 0);
    msr_kernel<32,32,16,true,false,true,4><<<dim3(ceil_div(12544,128),2), 128>>>(
        Oc, OSZ_C, x1c, BSc, 4*NBC, y1, nullptr, nullptr, 0,
        m2w1, m2b1, m2w2, m2b2, y2, 112, 56);
    msr_kernel<16,16,8,false,false,false,1><<<dim3(ceil_div(50176,128),2), 128>>>(
        nullptr, 0, nullptr, nullptr, 0, y2, nullptr, nullptr, 0,
        m3w1, m3b1, m3w2, m3b2, y3, 224, 112);
    msr_kernel<8,2,1,false,false,false,1><<<dim3(ceil_div(200704,128),2), 128>>>(
        nullptr, 0, nullptr, nullptr, 0, y3, nullptr, nullptr, 0,
        m4w1, m4b1, m4w2, m4b2, outp, 448, 224);

    (void)in_sizes; (void)n_in; (void)out_size;
}